// round 2
// baseline (speedup 1.0000x reference)
#include <cuda_runtime.h>
#include <cuda_bf16.h>
#include <math.h>

// Problem constants (fixed by the dataset)
#define BB 2
#define NN 1024
#define DD 1024
#define HH 16
#define HD 64
#define BH (BB*HH)     // 32
#define NT (NN/64)     // 16

// ---------------- scratch (device globals; no allocation allowed) -------------
__device__ float g_q[BB*NN*DD];
__device__ float g_k[BB*NN*DD];
__device__ float g_v[BB*NN*DD];
__device__ float g_w[BB*NN*DD];
__device__ float g_w1[BB*NN*HD];
__device__ float g_xb[BB*NN*HH];
__device__ float g_xf[BB*NN*HH];
__device__ float g_beta[BH*NN];
__device__ float g_Fc[BH*NN];
__device__ float g_C[(size_t)BH*NN*NN];   // 128 MB
__device__ float g_S[(size_t)BH*NN*NN];   // 128 MB (logits -> P in place)
__device__ float g_O[BB*NN*DD];

// ---------------- generic tiled SGEMM: C = A @ B (row-major) -----------------
__global__ void sgemm_k(const float* __restrict__ A, const float* __restrict__ B,
                        float* __restrict__ C, int M, int N, int K,
                        int lda, int ldb, int ldc) {
    __shared__ float As[16][65];   // As[k][m]
    __shared__ float Bs[16][65];   // Bs[k][n]
    int tid = threadIdx.x;
    int tx = tid & 15, ty = tid >> 4;
    int bm0 = blockIdx.x * 64, bn0 = blockIdx.y * 64;
    float acc[4][4] = {};
    for (int k0 = 0; k0 < K; k0 += 16) {
        for (int i = tid; i < 64*16; i += 256) {
            int r = i >> 4, c = i & 15;
            int gr = bm0 + r, gc = k0 + c;
            As[c][r] = (gr < M && gc < K) ? A[(size_t)gr*lda + gc] : 0.f;
        }
        for (int i = tid; i < 16*64; i += 256) {
            int r = i >> 6, c = i & 63;
            int gr = k0 + r, gc = bn0 + c;
            Bs[r][c] = (gr < K && gc < N) ? B[(size_t)gr*ldb + gc] : 0.f;
        }
        __syncthreads();
        #pragma unroll
        for (int kk = 0; kk < 16; kk++) {
            float a[4], b[4];
            #pragma unroll
            for (int i = 0; i < 4; i++) a[i] = As[kk][ty*4+i];
            #pragma unroll
            for (int j = 0; j < 4; j++) b[j] = Bs[kk][tx*4+j];
            #pragma unroll
            for (int i = 0; i < 4; i++)
                #pragma unroll
                for (int j = 0; j < 4; j++) acc[i][j] = fmaf(a[i], b[j], acc[i][j]);
        }
        __syncthreads();
    }
    #pragma unroll
    for (int i = 0; i < 4; i++) {
        int gr = bm0 + ty*4 + i;
        if (gr >= M) continue;
        #pragma unroll
        for (int j = 0; j < 4; j++) {
            int gc = bn0 + tx*4 + j;
            if (gc < N) C[(size_t)gr*ldc + gc] = acc[i][j];
        }
    }
}

// ---- 64x64x64 register-tile GEMM helpers over pitch-65 smem operands --------
// As[k*65 + m], Bs[k*65 + n]; each thread owns 4x4 at (ty4.., tx4..)
__device__ __forceinline__ void mm64_add(const float* __restrict__ As,
                                         const float* __restrict__ Bs,
                                         float (&acc)[4][4], int ty4, int tx4) {
    #pragma unroll 16
    for (int kk = 0; kk < 64; kk++) {
        float a[4], b[4];
        #pragma unroll
        for (int i = 0; i < 4; i++) a[i] = As[kk*65 + ty4 + i];
        #pragma unroll
        for (int j = 0; j < 4; j++) b[j] = Bs[kk*65 + tx4 + j];
        #pragma unroll
        for (int i = 0; i < 4; i++)
            #pragma unroll
            for (int j = 0; j < 4; j++) acc[i][j] = fmaf(a[i], b[j], acc[i][j]);
    }
}
__device__ __forceinline__ void mm64_sub(const float* __restrict__ As,
                                         const float* __restrict__ Bs,
                                         float (&acc)[4][4], int ty4, int tx4) {
    #pragma unroll 16
    for (int kk = 0; kk < 64; kk++) {
        float a[4], b[4];
        #pragma unroll
        for (int i = 0; i < 4; i++) a[i] = As[kk*65 + ty4 + i];
        #pragma unroll
        for (int j = 0; j < 4; j++) b[j] = Bs[kk*65 + tx4 + j];
        #pragma unroll
        for (int i = 0; i < 4; i++)
            #pragma unroll
            for (int j = 0; j < 4; j++) acc[i][j] = fmaf(-a[i], b[j], acc[i][j]);
    }
}

// ---------------- l2-normalize w per (b,t,h) over hd=64 ----------------------
__global__ void normw_k() {
    int wid = (blockIdx.x * blockDim.x + threadIdx.x) >> 5;
    int lane = threadIdx.x & 31;
    if (wid >= BB*NN*HH) return;
    int h = wid % HH;
    int t = (wid / HH) % NN;
    int b = wid / (HH*NN);
    float* base = g_w + (size_t)(b*NN + t)*DD + h*HD;
    float v0 = base[lane], v1 = base[lane+32];
    float ss = v0*v0 + v1*v1;
    #pragma unroll
    for (int o = 16; o; o >>= 1) ss += __shfl_xor_sync(0xffffffffu, ss, o);
    float r = rsqrtf(ss + 1e-6f);
    base[lane] = v0*r; base[lane+32] = v1*r;
}

// ---------------- beta = 2*sigmoid(x@Wb); logf = logsigmoid(x@Wf + delta) ----
__global__ void gates_k(const float* __restrict__ delta) {
    int idx = blockIdx.x * blockDim.x + threadIdx.x;
    if (idx >= BB*NN*HH) return;
    int h = idx % HH;
    int t = (idx / HH) % NN;
    int b = idx / (HH*NN);
    float xb = g_xb[idx];
    float beta = 2.f / (1.f + expf(-xb));
    float z = g_xf[idx] + delta[h];
    float lf = fminf(z, 0.f) - log1pf(expf(-fabsf(z)));
    int bh = b*HH + h;
    g_beta[bh*NN + t] = beta;
    g_Fc[bh*NN + t] = lf;   // cumsum'd in place next
}

// inclusive scan over n per (b,h)
__global__ void cumsum_k() {
    __shared__ float buf[NN];
    int bh = blockIdx.x, t = threadIdx.x;
    buf[t] = g_Fc[bh*NN + t];
    __syncthreads();
    for (int o = 1; o < NN; o <<= 1) {
        float add = (t >= o) ? buf[t - o] : 0.f;
        __syncthreads();
        buf[t] += add;
        __syncthreads();
    }
    g_Fc[bh*NN + t] = buf[t];
}

// ---------------- blocked unit-lower triangular solve ------------------------
// Step ib computes C block-row ib for every column tile ct <= ib:
//   C[ib][ct] = (I + L_ii)^{-1} ( M[ib][ct] - sum_{ct<=j<ib} L[ib][j] C[j][ct] )
// L tiles recomputed from W on the fly. grid = (ct in [0, ib], bh).
__global__ void solve_k(int ib) {
    extern __shared__ float sm[];
    float* Wis  = sm;             // [64][65] As-layout: Wis[dd*65 + r] = w[ib*64+r][dd]
    float* BufB = sm + 4160;      // [64][65] Bs-layout
    float* Ls   = sm + 2*4160;    // [64][65]
    float* Css  = sm + 3*4160;    // [64][65]
    __shared__ float betaS[64];
    __shared__ float betaI[64];
    int ct = blockIdx.x;
    int bh = blockIdx.y;
    int b = bh / HH, h = bh % HH;
    int tid = threadIdx.x, tx4 = (tid & 15) * 4, ty4 = (tid >> 4) * 4;
    size_t xbase = (size_t)b*NN*DD + (size_t)h*HD;
    size_t Cbase = (size_t)bh*NN*NN;

    for (int i = tid; i < 4096; i += 256) {
        int r = i >> 6, dd = i & 63;
        Wis[dd*65 + r] = g_w[xbase + (size_t)(ib*64 + r)*DD + dd];
    }
    for (int i = tid; i < 4096; i += 256) {
        int c = i >> 6, dd = i & 63;
        BufB[dd*65 + c] = g_k[xbase + (size_t)(ct*64 + c)*DD + dd];
    }
    if (tid < 64) betaI[tid] = g_beta[bh*NN + ib*64 + tid];
    __syncthreads();

    float acc[4][4] = {};
    mm64_add(Wis, BufB, acc, ty4, tx4);      // M tile = W_ib K_ct^T

    for (int j = ct; j < ib; j++) {
        __syncthreads();
        for (int i = tid; i < 4096; i += 256) {
            int c = i >> 6, dd = i & 63;
            BufB[dd*65 + c] = g_w[xbase + (size_t)(j*64 + c)*DD + dd];
        }
        for (int i = tid; i < 4096; i += 256) {
            int s = i >> 6, c = i & 63;
            Css[s*65 + c] = g_C[Cbase + (size_t)(j*64 + s)*NN + ct*64 + c];
        }
        if (tid < 64) betaS[tid] = g_beta[bh*NN + j*64 + tid];
        __syncthreads();
        float t4[4][4] = {};
        mm64_add(Wis, BufB, t4, ty4, tx4);   // w_i . w_j
        #pragma unroll
        for (int i = 0; i < 4; i++)
            #pragma unroll
            for (int jj = 0; jj < 4; jj++)
                Ls[(tx4+jj)*65 + ty4 + i] = t4[i][jj] * betaS[tx4+jj];  // transposed store
        __syncthreads();
        mm64_sub(Ls, Css, acc, ty4, tx4);    // acc -= L_ij @ C_j
    }

    // ---- apply (I + L_ii)^{-1} via per-column forward substitution ----
    __syncthreads();   // protect Css/Ls against readers of the last loop iter
    // RHS into Css (diagonal tile: strictly-lower part only)
    #pragma unroll
    for (int i = 0; i < 4; i++)
        #pragma unroll
        for (int jj = 0; jj < 4; jj++) {
            int r = ty4 + i, c = tx4 + jj;
            float v = acc[i][jj];
            if (ct == ib && c >= r) v = 0.f;
            Css[r*65 + c] = v;
        }
    // L_ii = tril(beta_c * w_r.w_c, -1), rows/cols both in block ib
    {
        float t4[4][4] = {};
        mm64_add(Wis, Wis, t4, ty4, tx4);
        #pragma unroll
        for (int i = 0; i < 4; i++)
            #pragma unroll
            for (int jj = 0; jj < 4; jj++) {
                int r = ty4 + i, c = tx4 + jj;
                Ls[r*65 + c] = (c < r) ? t4[i][jj] * betaI[c] : 0.f;
            }
    }
    __syncthreads();
    if (tid < 64) {
        int c = tid;   // each thread owns one column: no cross-thread deps
        for (int r = 1; r < 64; r++) {
            float s = 0.f;
            for (int rp = 0; rp < r; rp++) s += Ls[r*65 + rp] * Css[rp*65 + c];
            Css[r*65 + c] -= s;
        }
    }
    __syncthreads();
    #pragma unroll
    for (int i = 0; i < 4; i++)
        #pragma unroll
        for (int jj = 0; jj < 4; jj++) {
            int r = ty4 + i, c = tx4 + jj;
            float v = Css[r*65 + c];
            if (ct == ib && c >= r) v = 0.f;
            g_C[Cbase + (size_t)(ib*64 + r)*NN + ct*64 + c] = v;
        }
}

// ---------------- logits: S = QK^T - tril(QW^T * beta) @ C, + decay, mask ----
__global__ void scores_k() {
    int tt = blockIdx.x, jt = blockIdx.y, bh = blockIdx.z;
    if (jt > tt) return;
    extern __shared__ float sm[];
    float* Qst  = sm;             // [dd][r]
    float* BufB = sm + 4160;      // [dd][c]
    float* Gs   = sm + 2*4160;    // [s][r]  (A-layout for second GEMM)
    float* Css  = sm + 3*4160;    // [s][c]
    __shared__ float betaS[64];
    __shared__ float FcT[64];
    __shared__ float FcJ[64];
    int b = bh / HH, h = bh % HH;
    int tid = threadIdx.x, tx4 = (tid & 15) * 4, ty4 = (tid >> 4) * 4;
    size_t xbase = (size_t)b*NN*DD + (size_t)h*HD;
    size_t Cbase = (size_t)bh*NN*NN;

    for (int i = tid; i < 4096; i += 256) {
        int r = i >> 6, dd = i & 63;
        Qst[dd*65 + r] = g_q[xbase + (size_t)(tt*64 + r)*DD + dd];
    }
    for (int i = tid; i < 4096; i += 256) {
        int c = i >> 6, dd = i & 63;
        BufB[dd*65 + c] = g_k[xbase + (size_t)(jt*64 + c)*DD + dd];
    }
    if (tid < 64) {
        FcT[tid] = g_Fc[bh*NN + tt*64 + tid];
        FcJ[tid] = g_Fc[bh*NN + jt*64 + tid];
    }
    __syncthreads();

    float acc[4][4] = {};
    mm64_add(Qst, BufB, acc, ty4, tx4);      // Q K^T

    for (int sb = jt; sb <= tt; sb++) {
        __syncthreads();
        for (int i = tid; i < 4096; i += 256) {
            int c = i >> 6, dd = i & 63;
            BufB[dd*65 + c] = g_w[xbase + (size_t)(sb*64 + c)*DD + dd];
        }
        for (int i = tid; i < 4096; i += 256) {
            int s = i >> 6, c = i & 63;
            Css[s*65 + c] = g_C[Cbase + (size_t)(sb*64 + s)*NN + jt*64 + c];
        }
        if (tid < 64) betaS[tid] = g_beta[bh*NN + sb*64 + tid];
        __syncthreads();
        float t4[4][4] = {};
        mm64_add(Qst, BufB, t4, ty4, tx4);   // q_t . w_s
        #pragma unroll
        for (int i = 0; i < 4; i++)
            #pragma unroll
            for (int jj = 0; jj < 4; jj++) {
                int r = ty4 + i, c = tx4 + jj;
                float g = t4[i][jj] * betaS[c];
                if (sb == tt && c > r) g = 0.f;          // tril(G) incl. diagonal
                Gs[c*65 + r] = g;                        // transposed store
            }
        __syncthreads();
        mm64_sub(Gs, Css, acc, ty4, tx4);    // acc -= G @ C
    }

    const float scale = 0.125f;  // 64^-0.5
    #pragma unroll
    for (int i = 0; i < 4; i++)
        #pragma unroll
        for (int jj = 0; jj < 4; jj++) {
            int r = ty4 + i, c = tx4 + jj;
            int gt = tt*64 + r, gj = jt*64 + c;
            float val;
            if (gj <= gt) val = acc[i][jj]*scale + FcT[r] - FcJ[c];
            else          val = -INFINITY;
            g_S[(size_t)bh*NN*NN + (size_t)gt*NN + gj] = val;
        }
}

// ---------------- causal softmax (rows of the written region only) -----------
__global__ void softmax_k() {
    int t = blockIdx.x, bh = blockIdx.y;
    int jmax = ((t >> 6) + 1) << 6;   // written region: full tiles up to t's tile
    float* row = g_S + (size_t)bh*NN*NN + (size_t)t*NN;
    __shared__ float red[256];
    int tid = threadIdx.x;
    float m = -INFINITY;
    for (int j = tid; j < jmax; j += 256) m = fmaxf(m, row[j]);
    red[tid] = m; __syncthreads();
    for (int o = 128; o; o >>= 1) { if (tid < o) red[tid] = fmaxf(red[tid], red[tid+o]); __syncthreads(); }
    m = red[0]; __syncthreads();
    float s = 0.f;
    for (int j = tid; j < jmax; j += 256) { float e = expf(row[j] - m); row[j] = e; s += e; }
    red[tid] = s; __syncthreads();
    for (int o = 128; o; o >>= 1) { if (tid < o) red[tid] += red[tid+o]; __syncthreads(); }
    float inv = 1.f / red[0];
    for (int j = tid; j < jmax; j += 256) row[j] *= inv;
}

// ---------------- O_h = P @ V_h (causal tiles only) --------------------------
__global__ void pv_k() {
    int tm = blockIdx.x, bh = blockIdx.y;
    int b = bh / HH, h = bh % HH;
    extern __shared__ float sm[];
    float* Ps = sm;          // [jj][r]
    float* Vs = sm + 4160;   // [jj][dd]
    int tid = threadIdx.x, tx4 = (tid & 15) * 4, ty4 = (tid >> 4) * 4;
    float acc[4][4] = {};
    for (int jt = 0; jt <= tm; jt++) {
        __syncthreads();
        for (int i = tid; i < 4096; i += 256) {
            int r = i >> 6, jj = i & 63;
            Ps[jj*65 + r] = g_S[(size_t)bh*NN*NN + (size_t)(tm*64 + r)*NN + jt*64 + jj];
        }
        for (int i = tid; i < 4096; i += 256) {
            int jj = i >> 6, dd = i & 63;
            Vs[jj*65 + dd] = g_v[(size_t)(b*NN + jt*64 + jj)*DD + h*HD + dd];
        }
        __syncthreads();
        mm64_add(Ps, Vs, acc, ty4, tx4);
    }
    #pragma unroll
    for (int i = 0; i < 4; i++)
        #pragma unroll
        for (int jj = 0; jj < 4; jj++)
            g_O[(size_t)(b*NN + tm*64 + ty4 + i)*DD + h*HD + tx4 + jj] = acc[i][jj];
}

// -----------------------------------------------------------------------------
extern "C" void kernel_launch(void* const* d_in, const int* in_sizes, int n_in,
                              void* d_out, int out_size) {
    const float* x     = (const float*)d_in[0];
    const float* Wq    = (const float*)d_in[1];
    const float* Wk    = (const float*)d_in[2];
    const float* Wv    = (const float*)d_in[3];
    const float* Wo    = (const float*)d_in[4];
    const float* Ww1   = (const float*)d_in[5];
    const float* Ww2   = (const float*)d_in[6];
    const float* Wb    = (const float*)d_in[7];
    const float* Wf    = (const float*)d_in[8];
    const float* delta = (const float*)d_in[9];
    float* out = (float*)d_out;

    cudaFuncSetAttribute(solve_k,  cudaFuncAttributeMaxDynamicSharedMemorySize, 4*4160*4);
    cudaFuncSetAttribute(scores_k, cudaFuncAttributeMaxDynamicSharedMemorySize, 4*4160*4);

    float *pq, *pk, *pv, *pw, *pw1, *pxb, *pxf, *pO;
    cudaGetSymbolAddress((void**)&pq,  g_q);
    cudaGetSymbolAddress((void**)&pk,  g_k);
    cudaGetSymbolAddress((void**)&pv,  g_v);
    cudaGetSymbolAddress((void**)&pw,  g_w);
    cudaGetSymbolAddress((void**)&pw1, g_w1);
    cudaGetSymbolAddress((void**)&pxb, g_xb);
    cudaGetSymbolAddress((void**)&pxf, g_xf);
    cudaGetSymbolAddress((void**)&pO,  g_O);

    const int M = BB*NN;   // 2048
    dim3 blk(256);
    dim3 gfull(M/64, DD/64);           // 32 x 16

    // projections
    sgemm_k<<<gfull, blk>>>(x, Wq, pq, M, DD, DD, DD, DD, DD);
    sgemm_k<<<gfull, blk>>>(x, Wk, pk, M, DD, DD, DD, DD, DD);
    sgemm_k<<<gfull, blk>>>(x, Wv, pv, M, DD, DD, DD, DD, DD);
    sgemm_k<<<dim3(M/64, 1), blk>>>(x, Ww1, pw1, M, HD, DD, DD, HD, HD);
    sgemm_k<<<gfull, blk>>>(pw1, Ww2, pw, M, DD, HD, HD, DD, DD);
    sgemm_k<<<dim3(M/64, 1), blk>>>(x, Wb, pxb, M, HH, DD, DD, HH, HH);
    sgemm_k<<<dim3(M/64, 1), blk>>>(x, Wf, pxf, M, HH, DD, DD, HH, HH);

    // w normalize, gates, decay cumsum
    normw_k<<<(BB*NN*HH*32)/256, 256>>>();
    gates_k<<<(BB*NN*HH + 255)/256, 256>>>(delta);
    cumsum_k<<<BH, NN>>>();

    // blocked UT triangular solve: 16 sequential block-row steps
    size_t smem4 = 4*4160*sizeof(float);
    for (int ib = 0; ib < NT; ib++)
        solve_k<<<dim3(ib + 1, BH), 256, smem4>>>(ib);

    // logits, softmax, P@V, output projection
    scores_k<<<dim3(NT, NT, BH), 256, smem4>>>();
    softmax_k<<<dim3(NN, BH), 256>>>();
    pv_k<<<dim3(NT, BH), 256, 2*4160*sizeof(float)>>>();
    sgemm_k<<<gfull, blk>>>(pO, Wo, out, M, DD, DD, DD, DD, DD);
}

// round 5
// speedup vs baseline: 1.4019x; 1.4019x over previous
#include <cuda_runtime.h>
#include <cuda_bf16.h>
#include <math.h>

// Problem constants (fixed by the dataset)
#define BB 2
#define NN 1024
#define DD 1024
#define HH 16
#define HD 64
#define BH (BB*HH)     // 32
#define NT (NN/64)     // 16

// ---------------- scratch (device globals; no allocation allowed) -------------
__device__ float g_q[BB*NN*DD];
__device__ float g_k[BB*NN*DD];
__device__ float g_v[BB*NN*DD];
__device__ float g_w[BB*NN*DD];
__device__ float g_w1[BB*NN*HD];
__device__ float g_xb[BB*NN*HH];
__device__ float g_xf[BB*NN*HH];
__device__ float g_beta[BH*NN];
__device__ float g_Fc[BH*NN];
__device__ float g_C[(size_t)BH*NN*NN];   // 128 MB (RHS -> solved C in place)
__device__ float g_L[(size_t)BH*NN*NN];   // 128 MB precomputed L tiles
__device__ float g_G[(size_t)BH*NN*NN];   // 128 MB precomputed G tiles
__device__ float g_S[(size_t)BH*NN*NN];   // 128 MB (logits -> P in place)
__device__ float g_O[BB*NN*DD];
__device__ float g_part[8*2048*96];       // split-K partials for skinny projections

// ---------------- generic tiled SGEMM: C = A @ B (row-major) -----------------
__global__ void sgemm_k(const float* __restrict__ A, const float* __restrict__ B,
                        float* __restrict__ C, int M, int N, int K,
                        int lda, int ldb, int ldc) {
    __shared__ float As[16][65];   // As[k][m]
    __shared__ float Bs[16][65];   // Bs[k][n]
    int tid = threadIdx.x;
    int tx = tid & 15, ty = tid >> 4;
    int bm0 = blockIdx.x * 64, bn0 = blockIdx.y * 64;
    float acc[4][4] = {};
    for (int k0 = 0; k0 < K; k0 += 16) {
        for (int i = tid; i < 64*16; i += 256) {
            int r = i >> 4, c = i & 15;
            int gr = bm0 + r, gc = k0 + c;
            As[c][r] = (gr < M && gc < K) ? A[(size_t)gr*lda + gc] : 0.f;
        }
        for (int i = tid; i < 16*64; i += 256) {
            int r = i >> 6, c = i & 63;
            int gr = k0 + r, gc = bn0 + c;
            Bs[r][c] = (gr < K && gc < N) ? B[(size_t)gr*ldb + gc] : 0.f;
        }
        __syncthreads();
        #pragma unroll
        for (int kk = 0; kk < 16; kk++) {
            float a[4], b[4];
            #pragma unroll
            for (int i = 0; i < 4; i++) a[i] = As[kk][ty*4+i];
            #pragma unroll
            for (int j = 0; j < 4; j++) b[j] = Bs[kk][tx*4+j];
            #pragma unroll
            for (int i = 0; i < 4; i++)
                #pragma unroll
                for (int j = 0; j < 4; j++) acc[i][j] = fmaf(a[i], b[j], acc[i][j]);
        }
        __syncthreads();
    }
    #pragma unroll
    for (int i = 0; i < 4; i++) {
        int gr = bm0 + ty*4 + i;
        if (gr >= M) continue;
        #pragma unroll
        for (int j = 0; j < 4; j++) {
            int gc = bn0 + tx*4 + j;
            if (gc < N) C[(size_t)gr*ldc + gc] = acc[i][j];
        }
    }
}

// ---- 64x64x64 register-tile GEMM helpers over pitch-65 smem operands --------
// As[k*65 + m], Bs[k*65 + n]; each thread owns 4x4 at (ty4.., tx4..)
__device__ __forceinline__ void mm64_add(const float* __restrict__ As,
                                         const float* __restrict__ Bs,
                                         float (&acc)[4][4], int ty4, int tx4) {
    #pragma unroll 16
    for (int kk = 0; kk < 64; kk++) {
        float a[4], b[4];
        #pragma unroll
        for (int i = 0; i < 4; i++) a[i] = As[kk*65 + ty4 + i];
        #pragma unroll
        for (int j = 0; j < 4; j++) b[j] = Bs[kk*65 + tx4 + j];
        #pragma unroll
        for (int i = 0; i < 4; i++)
            #pragma unroll
            for (int j = 0; j < 4; j++) acc[i][j] = fmaf(a[i], b[j], acc[i][j]);
    }
}
__device__ __forceinline__ void mm64_sub(const float* __restrict__ As,
                                         const float* __restrict__ Bs,
                                         float (&acc)[4][4], int ty4, int tx4) {
    #pragma unroll 16
    for (int kk = 0; kk < 64; kk++) {
        float a[4], b[4];
        #pragma unroll
        for (int i = 0; i < 4; i++) a[i] = As[kk*65 + ty4 + i];
        #pragma unroll
        for (int j = 0; j < 4; j++) b[j] = Bs[kk*65 + tx4 + j];
        #pragma unroll
        for (int i = 0; i < 4; i++)
            #pragma unroll
            for (int j = 0; j < 4; j++) acc[i][j] = fmaf(-a[i], b[j], acc[i][j]);
    }
}

// tile loaders: 64x64 tiles, 256 threads. ldg = row stride in gmem.
// transposed: s[c*65 + r] = g[r*ldg + c]   (use for contraction-over-c layouts)
__device__ __forceinline__ void load_tile_T(const float* __restrict__ g, int ldg,
                                            float* __restrict__ s, int tid) {
    for (int i = tid; i < 4096; i += 256) {
        int r = i >> 6, c = i & 63;
        s[c*65 + r] = g[(size_t)r*ldg + c];
    }
}
// straight: s[r*65 + c] = g[r*ldg + c]
__device__ __forceinline__ void load_tile(const float* __restrict__ g, int ldg,
                                          float* __restrict__ s, int tid) {
    for (int i = tid; i < 4096; i += 256) {
        int r = i >> 6, c = i & 63;
        s[r*65 + c] = g[(size_t)r*ldg + c];
    }
}

// ------------- fused skinny projections: x @ [Ww1 | Wb | Wf], split-K --------
__global__ void proj_small_k(const float* __restrict__ x,
                             const float* __restrict__ Ww1,
                             const float* __restrict__ Wb,
                             const float* __restrict__ Wf) {
    extern __shared__ float sm[];
    float* As = sm;            // [128][65]: As[k*65+m]
    float* Bs = sm + 128*65;   // [128][100]: Bs[k*100+c]
    int mt = blockIdx.x, kc = blockIdx.y;
    int tid = threadIdx.x, tx = tid & 15, ty = tid >> 4;
    int m0 = mt*64, k0 = kc*128;
    for (int i = tid; i < 64*128; i += 256) {
        int m = i >> 7, kk = i & 127;
        As[kk*65 + m] = x[(size_t)(m0+m)*DD + k0 + kk];
    }
    for (int i = tid; i < 128*96; i += 256) {
        int kk = i / 96, c = i - kk*96;
        int kg = k0 + kk;
        float v;
        if (c < 64)      v = Ww1[kg*64 + c];
        else if (c < 80) v = Wb[kg*16 + (c-64)];
        else             v = Wf[kg*16 + (c-80)];
        Bs[kk*100 + c] = v;
    }
    __syncthreads();
    float acc[4][6] = {};
    #pragma unroll 8
    for (int kk = 0; kk < 128; kk++) {
        float a[4], b[6];
        #pragma unroll
        for (int i = 0; i < 4; i++) a[i] = As[kk*65 + ty*4 + i];
        #pragma unroll
        for (int j = 0; j < 6; j++) b[j] = Bs[kk*100 + tx*6 + j];
        #pragma unroll
        for (int i = 0; i < 4; i++)
            #pragma unroll
            for (int j = 0; j < 6; j++) acc[i][j] = fmaf(a[i], b[j], acc[i][j]);
    }
    float* dst = g_part + ((size_t)kc*2048 + m0)*96;
    #pragma unroll
    for (int i = 0; i < 4; i++)
        #pragma unroll
        for (int j = 0; j < 6; j++)
            dst[(size_t)(ty*4+i)*96 + tx*6 + j] = acc[i][j];
}
__global__ void proj_small_reduce_k() {
    int idx = blockIdx.x*256 + threadIdx.x;
    if (idx >= 2048*96) return;
    float s = 0.f;
    #pragma unroll
    for (int kc = 0; kc < 8; kc++) s += g_part[(size_t)kc*2048*96 + idx];
    int row = idx / 96, c = idx - (idx/96)*96;
    if (c < 64)      g_w1[row*64 + c] = s;
    else if (c < 80) g_xb[row*16 + (c-64)] = s;
    else             g_xf[row*16 + (c-80)] = s;
}

// ---------------- l2-normalize w per (b,t,h) over hd=64 ----------------------
__global__ void normw_k() {
    int wid = (blockIdx.x * blockDim.x + threadIdx.x) >> 5;
    int lane = threadIdx.x & 31;
    if (wid >= BB*NN*HH) return;
    int h = wid % HH;
    int t = (wid / HH) % NN;
    int b = wid / (HH*NN);
    float* base = g_w + (size_t)(b*NN + t)*DD + h*HD;
    float v0 = base[lane], v1 = base[lane+32];
    float ss = v0*v0 + v1*v1;
    #pragma unroll
    for (int o = 16; o; o >>= 1) ss += __shfl_xor_sync(0xffffffffu, ss, o);
    float r = rsqrtf(ss + 1e-6f);
    base[lane] = v0*r; base[lane+32] = v1*r;
}

// ---------------- beta = 2*sigmoid(x@Wb); logf = logsigmoid(x@Wf + delta) ----
__global__ void gates_k(const float* __restrict__ delta) {
    int idx = blockIdx.x * blockDim.x + threadIdx.x;
    if (idx >= BB*NN*HH) return;
    int h = idx % HH;
    int t = (idx / HH) % NN;
    int b = idx / (HH*NN);
    float xb = g_xb[idx];
    float beta = 2.f / (1.f + expf(-xb));
    float z = g_xf[idx] + delta[h];
    float lf = fminf(z, 0.f) - log1pf(expf(-fabsf(z)));
    int bh = b*HH + h;
    g_beta[bh*NN + t] = beta;
    g_Fc[bh*NN + t] = lf;   // cumsum'd in place next
}

// inclusive scan over n per (b,h)
__global__ void cumsum_k() {
    __shared__ float buf[NN];
    int bh = blockIdx.x, t = threadIdx.x;
    buf[t] = g_Fc[bh*NN + t];
    __syncthreads();
    for (int o = 1; o < NN; o <<= 1) {
        float add = (t >= o) ? buf[t - o] : 0.f;
        __syncthreads();
        buf[t] += add;
        __syncthreads();
    }
    g_Fc[bh*NN + t] = buf[t];
}

// ------------- precompute masked rank-64 tile products -----------------------
// Out[ti][tj] = mask( A_rows(ti) @ B_rows(tj)^T ) * (useBeta ? beta[col] : 1)
// diagKeepEq=0: keep c<r on diag tile (strict lower). =1: keep c<=r.
__global__ void pre_k(const float* __restrict__ Abase, const float* __restrict__ Bbase,
                      float* __restrict__ Out, int diagKeepEq, int useBeta) {
    int ti = blockIdx.x, tj = blockIdx.y, bh = blockIdx.z;
    if (tj > ti) return;
    extern __shared__ float sm[];
    float* As = sm; float* Bs = sm + 4160;
    __shared__ float betaS[64];
    int b = bh / HH, h = bh % HH;
    int tid = threadIdx.x, tx4 = (tid & 15)*4, ty4 = (tid >> 4)*4;
    size_t xbase = (size_t)b*NN*DD + (size_t)h*HD;
    load_tile_T(Abase + xbase + (size_t)(ti*64)*DD, DD, As, tid);
    load_tile_T(Bbase + xbase + (size_t)(tj*64)*DD, DD, Bs, tid);
    if (tid < 64) betaS[tid] = useBeta ? g_beta[bh*NN + tj*64 + tid] : 1.f;
    __syncthreads();
    float acc[4][4] = {};
    mm64_add(As, Bs, acc, ty4, tx4);
    float* dst = Out + (size_t)bh*NN*NN + (size_t)(ti*64)*NN + tj*64;
    bool diag = (ti == tj);
    #pragma unroll
    for (int i = 0; i < 4; i++)
        #pragma unroll
        for (int j = 0; j < 4; j++) {
            int r = ty4 + i, c = tx4 + j;
            float v = acc[i][j] * betaS[c];
            if (diag && (diagKeepEq ? (c > r) : (c >= r))) v = 0.f;
            dst[(size_t)r*NN + c] = v;
        }
}

// ---------------- blocked unit-lower triangular solve ------------------------
// C[ib][ct] = (I+L_ii)^{-1} ( C[ib][ct] - sum_{ct<=j<ib} L[ib][j] C[j][ct] )
__global__ void solve2_k(int ib) {
    int ct = blockIdx.x, bh = blockIdx.y;
    extern __shared__ float sm[];
    float* Ls  = sm;          // rotating A buffer
    float* Css = sm + 4160;   // rotating B buffer
    int tid = threadIdx.x, tx4 = (tid & 15)*4, ty4 = (tid >> 4)*4;
    size_t Cb = (size_t)bh*NN*NN;
    const float* rhs = g_C + Cb + (size_t)(ib*64)*NN + ct*64;
    float acc[4][4];
    #pragma unroll
    for (int i = 0; i < 4; i++)
        #pragma unroll
        for (int j = 0; j < 4; j++)
            acc[i][j] = rhs[(size_t)(ty4+i)*NN + tx4 + j];

    for (int j = ct; j < ib; j++) {
        __syncthreads();
        load_tile_T(g_L + Cb + (size_t)(ib*64)*NN + j*64, NN, Ls, tid);   // As[s][r]=L[r][s]
        load_tile (g_C + Cb + (size_t)(j*64)*NN + ct*64, NN, Css, tid);   // Bs[s][c]=C[s][c]
        __syncthreads();
        mm64_sub(Ls, Css, acc, ty4, tx4);
    }

    // diag: x = (I+L_ii)^{-1} acc  via per-column forward substitution
    __syncthreads();
    load_tile(g_L + Cb + (size_t)(ib*64)*NN + ib*64, NN, Ls, tid);        // row-major L_ii
    #pragma unroll
    for (int i = 0; i < 4; i++)
        #pragma unroll
        for (int j = 0; j < 4; j++)
            Css[(ty4+i)*65 + tx4 + j] = acc[i][j];
    __syncthreads();
    if (tid < 64) {
        int c = tid;
        for (int r = 1; r < 64; r++) {
            float s0 = 0.f, s1 = 0.f, s2 = 0.f, s3 = 0.f;
            int rp = 0;
            for (; rp + 3 < r; rp += 4) {
                s0 += Ls[r*65 + rp    ] * Css[(rp    )*65 + c];
                s1 += Ls[r*65 + rp + 1] * Css[(rp + 1)*65 + c];
                s2 += Ls[r*65 + rp + 2] * Css[(rp + 2)*65 + c];
                s3 += Ls[r*65 + rp + 3] * Css[(rp + 3)*65 + c];
            }
            for (; rp < r; rp++) s0 += Ls[r*65 + rp] * Css[rp*65 + c];
            Css[r*65 + c] -= (s0 + s1) + (s2 + s3);
        }
    }
    __syncthreads();
    float* dst = g_C + Cb + (size_t)(ib*64)*NN + ct*64;
    #pragma unroll
    for (int i = 0; i < 4; i++)
        #pragma unroll
        for (int j = 0; j < 4; j++)
            dst[(size_t)(ty4+i)*NN + tx4 + j] = Css[(ty4+i)*65 + tx4 + j];
}

// ---------------- logits: S = QK^T - G @ C, + decay, mask --------------------
__global__ void scores2_k() {
    int tt = blockIdx.x, jt = blockIdx.y, bh = blockIdx.z;
    if (jt > tt) return;
    extern __shared__ float sm[];
    float* Qst  = sm;             // persistent Q^T tile
    float* BufA = sm + 4160;      // K^T then G^T tiles
    float* BufB = sm + 2*4160;    // C tiles
    __shared__ float FcT[64], FcJ[64];
    int b = bh / HH, h = bh % HH;
    int tid = threadIdx.x, tx4 = (tid & 15)*4, ty4 = (tid >> 4)*4;
    size_t xbase = (size_t)b*NN*DD + (size_t)h*HD;
    size_t Cb = (size_t)bh*NN*NN;

    load_tile_T(g_q + xbase + (size_t)(tt*64)*DD, DD, Qst, tid);
    load_tile_T(g_k + xbase + (size_t)(jt*64)*DD, DD, BufA, tid);
    if (tid < 64) {
        FcT[tid] = g_Fc[bh*NN + tt*64 + tid];
        FcJ[tid] = g_Fc[bh*NN + jt*64 + tid];
    }
    __syncthreads();

    float acc[4][4] = {};
    mm64_add(Qst, BufA, acc, ty4, tx4);      // Q K^T

    for (int sb = jt; sb <= tt; sb++) {
        __syncthreads();
        load_tile_T(g_G + Cb + (size_t)(tt*64)*NN + sb*64, NN, BufA, tid);  // As[s][r]=G[r][s]
        load_tile (g_C + Cb + (size_t)(sb*64)*NN + jt*64, NN, BufB, tid);   // Bs[s][c]
        __syncthreads();
        mm64_sub(BufA, BufB, acc, ty4, tx4); // acc -= G @ C
    }

    const float scale = 0.125f;  // 64^-0.5
    #pragma unroll
    for (int i = 0; i < 4; i++)
        #pragma unroll
        for (int j = 0; j < 4; j++) {
            int r = ty4 + i, c = tx4 + j;
            int gt = tt*64 + r, gj = jt*64 + c;
            float val;
            if (gj <= gt) val = acc[i][j]*scale + FcT[r] - FcJ[c];
            else          val = -INFINITY;
            g_S[(size_t)bh*NN*NN + (size_t)gt*NN + gj] = val;
        }
}

// ---------------- causal softmax (rows of the written region only) -----------
__global__ void softmax_k() {
    int t = blockIdx.x, bh = blockIdx.y;
    int jmax = ((t >> 6) + 1) << 6;   // written region: full tiles up to t's tile
    float* row = g_S + (size_t)bh*NN*NN + (size_t)t*NN;
    __shared__ float red[256];
    int tid = threadIdx.x;
    float m = -INFINITY;
    for (int j = tid; j < jmax; j += 256) m = fmaxf(m, row[j]);
    red[tid] = m; __syncthreads();
    for (int o = 128; o; o >>= 1) { if (tid < o) red[tid] = fmaxf(red[tid], red[tid+o]); __syncthreads(); }
    m = red[0]; __syncthreads();
    float s = 0.f;
    for (int j = tid; j < jmax; j += 256) { float e = expf(row[j] - m); row[j] = e; s += e; }
    red[tid] = s; __syncthreads();
    for (int o = 128; o; o >>= 1) { if (tid < o) red[tid] += red[tid+o]; __syncthreads(); }
    float inv = 1.f / red[0];
    for (int j = tid; j < jmax; j += 256) row[j] *= inv;
}

// ---------------- O_h = P @ V_h (causal tiles only) --------------------------
__global__ void pv_k() {
    int tm = blockIdx.x, bh = blockIdx.y;
    int b = bh / HH, h = bh % HH;
    extern __shared__ float sm[];
    float* Ps = sm;          // [jj][r]
    float* Vs = sm + 4160;   // [jj][dd]
    int tid = threadIdx.x, tx4 = (tid & 15)*4, ty4 = (tid >> 4)*4;
    float acc[4][4] = {};
    for (int jt = 0; jt <= tm; jt++) {
        __syncthreads();
        load_tile_T(g_S + (size_t)bh*NN*NN + (size_t)(tm*64)*NN + jt*64, NN, Ps, tid);
        load_tile (g_v + (size_t)(b*NN + jt*64)*DD + h*HD, DD, Vs, tid);
        __syncthreads();
        mm64_add(Ps, Vs, acc, ty4, tx4);
    }
    #pragma unroll
    for (int i = 0; i < 4; i++)
        #pragma unroll
        for (int j = 0; j < 4; j++)
            g_O[(size_t)(b*NN + tm*64 + ty4 + i)*DD + h*HD + tx4 + j] = acc[i][j];
}

// -----------------------------------------------------------------------------
extern "C" void kernel_launch(void* const* d_in, const int* in_sizes, int n_in,
                              void* d_out, int out_size) {
    const float* x     = (const float*)d_in[0];
    const float* Wq    = (const float*)d_in[1];
    const float* Wk    = (const float*)d_in[2];
    const float* Wv    = (const float*)d_in[3];
    const float* Wo    = (const float*)d_in[4];
    const float* Ww1   = (const float*)d_in[5];
    const float* Ww2   = (const float*)d_in[6];
    const float* Wb    = (const float*)d_in[7];
    const float* Wf    = (const float*)d_in[8];
    const float* delta = (const float*)d_in[9];
    float* out = (float*)d_out;

    static bool attr_done = false;
    if (!attr_done) {
        cudaFuncSetAttribute(proj_small_k, cudaFuncAttributeMaxDynamicSharedMemorySize, (128*65 + 128*100)*4);
        cudaFuncSetAttribute(scores2_k,    cudaFuncAttributeMaxDynamicSharedMemorySize, 3*4160*4);
        attr_done = true;
    }

    float *pq, *pk, *pv, *pw, *pw1, *pO;
    cudaGetSymbolAddress((void**)&pq,  g_q);
    cudaGetSymbolAddress((void**)&pk,  g_k);
    cudaGetSymbolAddress((void**)&pv,  g_v);
    cudaGetSymbolAddress((void**)&pw,  g_w);
    cudaGetSymbolAddress((void**)&pw1, g_w1);
    cudaGetSymbolAddress((void**)&pO,  g_O);
    float *pC, *pL, *pG;
    cudaGetSymbolAddress((void**)&pC, g_C);
    cudaGetSymbolAddress((void**)&pL, g_L);
    cudaGetSymbolAddress((void**)&pG, g_G);

    const int M = BB*NN;   // 2048
    dim3 blk(256);
    dim3 gfull(M/64, DD/64);           // 32 x 16

    // big projections
    sgemm_k<<<gfull, blk>>>(x, Wq, pq, M, DD, DD, DD, DD, DD);
    sgemm_k<<<gfull, blk>>>(x, Wk, pk, M, DD, DD, DD, DD, DD);
    sgemm_k<<<gfull, blk>>>(x, Wv, pv, M, DD, DD, DD, DD, DD);

    // fused skinny projections (w1 | xb | xf), split-K + reduce
    proj_small_k<<<dim3(M/64, 8), blk, (128*65 + 128*100)*4>>>(x, Ww1, Wb, Wf);
    proj_small_reduce_k<<<(2048*96 + 255)/256, 256>>>();

    // w = w1 @ Ww2
    sgemm_k<<<gfull, blk>>>(pw1, Ww2, pw, M, DD, HD, HD, DD, DD);

    // w normalize, gates, decay cumsum
    normw_k<<<(BB*NN*HH*32)/256, 256>>>();
    gates_k<<<(BB*NN*HH + 255)/256, 256>>>(delta);
    cumsum_k<<<BH, NN>>>();

    // precompute RHS (M -> g_C), L, G   (parallel batched tile products)
    size_t smem2 = 2*4160*sizeof(float);
    dim3 gpre(NT, NT, BH);
    pre_k<<<gpre, blk, smem2>>>(pw, pk, pC, /*diagKeepEq=*/0, /*useBeta=*/0);  // Mlow
    pre_k<<<gpre, blk, smem2>>>(pw, pw, pL, /*diagKeepEq=*/0, /*useBeta=*/1);  // L
    pre_k<<<gpre, blk, smem2>>>(pq, pw, pG, /*diagKeepEq=*/1, /*useBeta=*/1);  // G

    // blocked UT triangular solve: 16 sequential block-row steps
    for (int ib = 0; ib < NT; ib++)
        solve2_k<<<dim3(ib + 1, BH), blk, smem2>>>(ib);

    // logits, softmax, P@V, output projection
    scores2_k<<<dim3(NT, NT, BH), blk, 3*4160*sizeof(float)>>>();
    softmax_k<<<dim3(NN, BH), 256>>>();
    pv_k<<<dim3(NT, BH), blk, smem2>>>();
    sgemm_k<<<gfull, blk>>>(pO, Wo, out, M, DD, DD, DD, DD, DD);
}

// round 7
// speedup vs baseline: 1.9280x; 1.3752x over previous
#include <cuda_runtime.h>
#include <cuda_bf16.h>
#include <math.h>

#define BB 2
#define NN 1024
#define DD 1024
#define HH 16
#define HD 64
#define BH (BB*HH)     // 32
#define NT (NN/64)     // 16
#define NTRI (NT*(NT+1)/2)   // 136
#define TP 68          // smem tile pitch (floats), 16B-aligned rows
#define TSZ (64*TP)    // 4352 floats = 17408 bytes per tile

// ---------------- scratch (device globals; no allocation allowed) -------------
__device__ float g_q[BB*NN*DD];
__device__ float g_k[BB*NN*DD];
__device__ float g_v[BB*NN*DD];
__device__ float g_w[BB*NN*DD];
__device__ float g_w1[BB*NN*HD];
__device__ float g_xb[BB*NN*HH];
__device__ float g_xf[BB*NN*HH];
__device__ float g_beta[BH*NN];
__device__ float g_Fc[BH*NN];
__device__ float g_C[(size_t)BH*NN*NN];   // RHS -> solved C in place (normal layout)
__device__ float g_L[(size_t)BH*NN*NN];   // L stored TRANSPOSED: g_L[s*NN+r] = L[r][s]
__device__ float g_G[(size_t)BH*NN*NN];   // G stored TRANSPOSED: g_G[s*NN+t] = G[t][s]
__device__ float g_S[(size_t)BH*NN*NN];   // logits -> P in place
__device__ float g_O[BB*NN*DD];
__device__ float g_part[8*2048*96];       // split-K partials for skinny projections

// ---------------- tile loaders: 64x64, 256 threads ---------------------------
// straight: s[r*TP + c] = g[r*ldg + c]   (float4 both sides)
__device__ __forceinline__ void load_f4(const float* __restrict__ g, int ldg,
                                        float* __restrict__ s, int tid) {
    #pragma unroll
    for (int v = 0; v < 4; v++) {
        int e = tid + v*256;            // 1024 float4 chunks
        int r = e >> 4, c4 = e & 15;
        float4 val = *(const float4*)(g + (size_t)r*ldg + c4*4);
        *(float4*)(s + r*TP + c4*4) = val;
    }
}
// transposed: s[c*TP + r] = g[r*ldg + c]  (float4 read, scalar smem writes)
__device__ __forceinline__ void load_T(const float* __restrict__ g, int ldg,
                                       float* __restrict__ s, int tid) {
    #pragma unroll
    for (int v = 0; v < 4; v++) {
        int e = tid + v*256;
        int r = e >> 4, c4 = e & 15;
        float4 val = *(const float4*)(g + (size_t)r*ldg + c4*4);
        s[(c4*4+0)*TP + r] = val.x;
        s[(c4*4+1)*TP + r] = val.y;
        s[(c4*4+2)*TP + r] = val.z;
        s[(c4*4+3)*TP + r] = val.w;
    }
}

// ---- 64x64x64 register-tile GEMM over pitch-TP smem, float4 operand loads ---
__device__ __forceinline__ void mm64_add(const float* __restrict__ As,
                                         const float* __restrict__ Bs,
                                         float (&acc)[4][4], int ty4, int tx4) {
    #pragma unroll 8
    for (int kk = 0; kk < 64; kk++) {
        float4 a = *(const float4*)(As + kk*TP + ty4);
        float4 b = *(const float4*)(Bs + kk*TP + tx4);
        float av[4] = {a.x, a.y, a.z, a.w};
        float bv[4] = {b.x, b.y, b.z, b.w};
        #pragma unroll
        for (int i = 0; i < 4; i++)
            #pragma unroll
            for (int j = 0; j < 4; j++) acc[i][j] = fmaf(av[i], bv[j], acc[i][j]);
    }
}
__device__ __forceinline__ void mm64_sub(const float* __restrict__ As,
                                         const float* __restrict__ Bs,
                                         float (&acc)[4][4], int ty4, int tx4) {
    #pragma unroll 8
    for (int kk = 0; kk < 64; kk++) {
        float4 a = *(const float4*)(As + kk*TP + ty4);
        float4 b = *(const float4*)(Bs + kk*TP + tx4);
        float av[4] = {a.x, a.y, a.z, a.w};
        float bv[4] = {b.x, b.y, b.z, b.w};
        #pragma unroll
        for (int i = 0; i < 4; i++)
            #pragma unroll
            for (int j = 0; j < 4; j++) acc[i][j] = fmaf(-av[i], bv[j], acc[i][j]);
    }
}

// triangular block index decode: t in [0, NTRI) -> (ti, tj), tj <= ti
__device__ __forceinline__ void tri_decode(int t, int& ti, int& tj) {
    int i = (int)((sqrtf(8.f*t + 1.f) - 1.f) * 0.5f);
    while ((i+1)*(i+2)/2 <= t) i++;
    while (i*(i+1)/2 > t) i--;
    ti = i; tj = t - i*(i+1)/2;
}

// ---------------- big SGEMM: C = A @ B, all dims multiples of 64 -------------
__global__ void sgemm64_k(const float* __restrict__ A, const float* __restrict__ B,
                          float* __restrict__ C, int K,
                          int lda, int ldb, int ldc) {
    extern __shared__ float sm[];
    float* As = sm;          // As[k][m]
    float* Bs = sm + TSZ;    // Bs[k][n]
    int tid = threadIdx.x, tx4 = (tid & 15)*4, ty4 = (tid >> 4)*4;
    int bm0 = blockIdx.x * 64, bn0 = blockIdx.y * 64;
    float acc[4][4] = {};
    for (int k0 = 0; k0 < K; k0 += 64) {
        load_T (A + (size_t)bm0*lda + k0, lda, As, tid);
        load_f4(B + (size_t)k0*ldb + bn0, ldb, Bs, tid);
        __syncthreads();
        mm64_add(As, Bs, acc, ty4, tx4);
        __syncthreads();
    }
    #pragma unroll
    for (int i = 0; i < 4; i++) {
        float4 o = make_float4(acc[i][0], acc[i][1], acc[i][2], acc[i][3]);
        *(float4*)(C + (size_t)(bm0 + ty4 + i)*ldc + bn0 + tx4) = o;
    }
}

// ------------- fused skinny projections: x @ [Ww1 | Wb | Wf], split-K --------
__global__ void proj_small_k(const float* __restrict__ x,
                             const float* __restrict__ Ww1,
                             const float* __restrict__ Wb,
                             const float* __restrict__ Wf) {
    extern __shared__ float sm[];
    float* As = sm;            // [128][65]
    float* Bs = sm + 128*65;   // [128][100]
    int mt = blockIdx.x, kc = blockIdx.y;
    int tid = threadIdx.x, tx = tid & 15, ty = tid >> 4;
    int m0 = mt*64, k0 = kc*128;
    for (int i = tid; i < 64*128; i += 256) {
        int m = i >> 7, kk = i & 127;
        As[kk*65 + m] = x[(size_t)(m0+m)*DD + k0 + kk];
    }
    for (int i = tid; i < 128*96; i += 256) {
        int kk = i / 96, c = i - kk*96;
        int kg = k0 + kk;
        float v;
        if (c < 64)      v = Ww1[kg*64 + c];
        else if (c < 80) v = Wb[kg*16 + (c-64)];
        else             v = Wf[kg*16 + (c-80)];
        Bs[kk*100 + c] = v;
    }
    __syncthreads();
    float acc[4][6] = {};
    #pragma unroll 8
    for (int kk = 0; kk < 128; kk++) {
        float a[4], b[6];
        #pragma unroll
        for (int i = 0; i < 4; i++) a[i] = As[kk*65 + ty*4 + i];
        #pragma unroll
        for (int j = 0; j < 6; j++) b[j] = Bs[kk*100 + tx*6 + j];
        #pragma unroll
        for (int i = 0; i < 4; i++)
            #pragma unroll
            for (int j = 0; j < 6; j++) acc[i][j] = fmaf(a[i], b[j], acc[i][j]);
    }
    float* dst = g_part + ((size_t)kc*2048 + m0)*96;
    #pragma unroll
    for (int i = 0; i < 4; i++)
        #pragma unroll
        for (int j = 0; j < 6; j++)
            dst[(size_t)(ty*4+i)*96 + tx*6 + j] = acc[i][j];
}
__global__ void proj_small_reduce_k() {
    int idx = blockIdx.x*256 + threadIdx.x;
    if (idx >= 2048*96) return;
    float s = 0.f;
    #pragma unroll
    for (int kc = 0; kc < 8; kc++) s += g_part[(size_t)kc*2048*96 + idx];
    int row = idx / 96, c = idx - (idx/96)*96;
    if (c < 64)      g_w1[row*64 + c] = s;
    else if (c < 80) g_xb[row*16 + (c-64)] = s;
    else             g_xf[row*16 + (c-80)] = s;
}

// ---------------- l2-normalize w per (b,t,h) over hd=64 ----------------------
__global__ void normw_k() {
    int wid = (blockIdx.x * blockDim.x + threadIdx.x) >> 5;
    int lane = threadIdx.x & 31;
    if (wid >= BB*NN*HH) return;
    int h = wid % HH;
    int t = (wid / HH) % NN;
    int b = wid / (HH*NN);
    float* base = g_w + (size_t)(b*NN + t)*DD + h*HD;
    float v0 = base[lane], v1 = base[lane+32];
    float ss = v0*v0 + v1*v1;
    #pragma unroll
    for (int o = 16; o; o >>= 1) ss += __shfl_xor_sync(0xffffffffu, ss, o);
    float r = rsqrtf(ss + 1e-6f);
    base[lane] = v0*r; base[lane+32] = v1*r;
}

// ---------------- beta = 2*sigmoid(x@Wb); logf = logsigmoid(x@Wf + delta) ----
__global__ void gates_k(const float* __restrict__ delta) {
    int idx = blockIdx.x * blockDim.x + threadIdx.x;
    if (idx >= BB*NN*HH) return;
    int h = idx % HH;
    int t = (idx / HH) % NN;
    int b = idx / (HH*NN);
    float xb = g_xb[idx];
    float beta = 2.f / (1.f + expf(-xb));
    float z = g_xf[idx] + delta[h];
    float lf = fminf(z, 0.f) - log1pf(expf(-fabsf(z)));
    int bh = b*HH + h;
    g_beta[bh*NN + t] = beta;
    g_Fc[bh*NN + t] = lf;
}

// inclusive scan over n per (b,h)
__global__ void cumsum_k() {
    __shared__ float buf[NN];
    int bh = blockIdx.x, t = threadIdx.x;
    buf[t] = g_Fc[bh*NN + t];
    __syncthreads();
    for (int o = 1; o < NN; o <<= 1) {
        float add = (t >= o) ? buf[t - o] : 0.f;
        __syncthreads();
        buf[t] += add;
        __syncthreads();
    }
    g_Fc[bh*NN + t] = buf[t];
}

// ------------- precompute masked rank-64 tile products -----------------------
// P[r][c] = A_row(ti*64+r) . B_row(tj*64+c), masked/beta'd.
// storeT=0: Out[(ti*64+r)*NN + tj*64+c] = v   (normal)
// storeT=1: Out[(tj*64+c)*NN + ti*64+r] = v   (transposed, coalesced via operand swap)
__global__ void pre_k(const float* __restrict__ Abase, const float* __restrict__ Bbase,
                      float* __restrict__ Out, int diagKeepEq, int useBeta, int storeT) {
    int ti, tj; tri_decode(blockIdx.x, ti, tj);
    int bh = blockIdx.y;
    extern __shared__ float sm[];
    float* As = sm; float* Bs = sm + TSZ;
    __shared__ float betaS[64];
    int b = bh / HH, h = bh % HH;
    int tid = threadIdx.x, tx4 = (tid & 15)*4, ty4 = (tid >> 4)*4;
    size_t xbase = (size_t)b*NN*DD + (size_t)h*HD;
    load_T(Abase + xbase + (size_t)(ti*64)*DD, DD, As, tid);   // As[d][r]
    load_T(Bbase + xbase + (size_t)(tj*64)*DD, DD, Bs, tid);   // Bs[d][c]
    if (tid < 64) betaS[tid] = useBeta ? g_beta[bh*NN + tj*64 + tid] : 1.f;
    __syncthreads();
    bool diag = (ti == tj);
    float acc[4][4] = {};
    if (!storeT) {
        mm64_add(As, Bs, acc, ty4, tx4);   // acc[i][j] = P[ty4+i][tx4+j]
        float* dst = Out + (size_t)bh*NN*NN + (size_t)(ti*64)*NN + tj*64;
        #pragma unroll
        for (int i = 0; i < 4; i++) {
            float v[4];
            #pragma unroll
            for (int j = 0; j < 4; j++) {
                int r = ty4 + i, c = tx4 + j;
                float x = acc[i][j] * betaS[c];
                if (diag && (diagKeepEq ? (c > r) : (c >= r))) x = 0.f;
                v[j] = x;
            }
            *(float4*)(dst + (size_t)(ty4+i)*NN + tx4) = make_float4(v[0],v[1],v[2],v[3]);
        }
    } else {
        mm64_add(Bs, As, acc, ty4, tx4);   // acc[i][j] = P[tx4+j][ty4+i]  (c_orig=ty4+i, r_orig=tx4+j)
        float* dst = Out + (size_t)bh*NN*NN + (size_t)(tj*64)*NN + ti*64;
        #pragma unroll
        for (int i = 0; i < 4; i++) {
            float v[4];
            #pragma unroll
            for (int j = 0; j < 4; j++) {
                int c_orig = ty4 + i, r_orig = tx4 + j;
                float x = acc[i][j] * betaS[c_orig];
                if (diag && (diagKeepEq ? (c_orig > r_orig) : (c_orig >= r_orig))) x = 0.f;
                v[j] = x;
            }
            *(float4*)(dst + (size_t)(ty4+i)*NN + tx4) = make_float4(v[0],v[1],v[2],v[3]);
        }
    }
}

// ---------------- blocked unit-lower triangular solve ------------------------
// C[ib][ct] = (I+L_ii)^{-1} ( C[ib][ct] - sum_{ct<=j<ib} L[ib][j] C[j][ct] )
// g_L holds L transposed: LT[s][r] = L[r][s].
__global__ void solve2_k(int ib) {
    int ct = blockIdx.x, bh = blockIdx.y;
    extern __shared__ float sm[];
    float* Ls  = sm;
    float* Css = sm + TSZ;
    int tid = threadIdx.x, tx4 = (tid & 15)*4, ty4 = (tid >> 4)*4;
    size_t Cb = (size_t)bh*NN*NN;
    const float* rhs = g_C + Cb + (size_t)(ib*64)*NN + ct*64;
    float acc[4][4];
    #pragma unroll
    for (int i = 0; i < 4; i++) {
        float4 v = *(const float4*)(rhs + (size_t)(ty4+i)*NN + tx4);
        acc[i][0]=v.x; acc[i][1]=v.y; acc[i][2]=v.z; acc[i][3]=v.w;
    }

    for (int j = ct; j < ib; j++) {
        __syncthreads();
        // As[s][r] = L[ib*64+r][j*64+s] = LT[(j*64+s)][ib*64+r]  -> straight load
        load_f4(g_L + Cb + (size_t)(j*64)*NN + ib*64, NN, Ls, tid);
        load_f4(g_C + Cb + (size_t)(j*64)*NN + ct*64, NN, Css, tid);
        __syncthreads();
        mm64_sub(Ls, Css, acc, ty4, tx4);
    }

    // diag: x = (I+L_ii)^{-1} acc ; Ls[s][r] = L[r][s]
    __syncthreads();
    load_f4(g_L + Cb + (size_t)(ib*64)*NN + ib*64, NN, Ls, tid);
    #pragma unroll
    for (int i = 0; i < 4; i++)
        #pragma unroll
        for (int j = 0; j < 4; j++)
            Css[(ty4+i)*TP + tx4 + j] = acc[i][j];
    __syncthreads();
    if (tid < 64) {
        int c = tid;
        for (int r = 1; r < 64; r++) {
            float s0 = 0.f, s1 = 0.f, s2 = 0.f, s3 = 0.f;
            int rp = 0;
            for (; rp + 3 < r; rp += 4) {
                s0 += Ls[(rp    )*TP + r] * Css[(rp    )*TP + c];
                s1 += Ls[(rp + 1)*TP + r] * Css[(rp + 1)*TP + c];
                s2 += Ls[(rp + 2)*TP + r] * Css[(rp + 2)*TP + c];
                s3 += Ls[(rp + 3)*TP + r] * Css[(rp + 3)*TP + c];
            }
            for (; rp < r; rp++) s0 += Ls[rp*TP + r] * Css[rp*TP + c];
            Css[r*TP + c] -= (s0 + s1) + (s2 + s3);
        }
    }
    __syncthreads();
    float* dst = g_C + Cb + (size_t)(ib*64)*NN + ct*64;
    #pragma unroll
    for (int i = 0; i < 4; i++) {
        float4 o = make_float4(Css[(ty4+i)*TP + tx4], Css[(ty4+i)*TP + tx4+1],
                               Css[(ty4+i)*TP + tx4+2], Css[(ty4+i)*TP + tx4+3]);
        *(float4*)(dst + (size_t)(ty4+i)*NN + tx4) = o;
    }
}

// ---------------- logits: S = QK^T - G @ C, + decay, mask --------------------
// g_G holds G transposed: GT[s][t] = G[t][s].
__global__ void scores2_k() {
    int tt, jt; tri_decode(blockIdx.x, tt, jt);
    int bh = blockIdx.y;
    extern __shared__ float sm[];
    float* Qst  = sm;             // persistent Q^T tile
    float* BufA = sm + TSZ;       // K^T then GT tiles
    float* BufB = sm + 2*TSZ;     // C tiles
    __shared__ float FcT[64], FcJ[64];
    int b = bh / HH, h = bh % HH;
    int tid = threadIdx.x, tx4 = (tid & 15)*4, ty4 = (tid >> 4)*4;
    size_t xbase = (size_t)b*NN*DD + (size_t)h*HD;
    size_t Cb = (size_t)bh*NN*NN;

    load_T(g_q + xbase + (size_t)(tt*64)*DD, DD, Qst, tid);
    load_T(g_k + xbase + (size_t)(jt*64)*DD, DD, BufA, tid);
    if (tid < 64) {
        FcT[tid] = g_Fc[bh*NN + tt*64 + tid];
        FcJ[tid] = g_Fc[bh*NN + jt*64 + tid];
    }
    __syncthreads();

    float acc[4][4] = {};
    mm64_add(Qst, BufA, acc, ty4, tx4);      // Q K^T

    for (int sb = jt; sb <= tt; sb++) {
        __syncthreads();
        // As[s][r] = G[tt*64+r][sb*64+s] = GT[(sb*64+s)][tt*64+r] -> straight
        load_f4(g_G + Cb + (size_t)(sb*64)*NN + tt*64, NN, BufA, tid);
        load_f4(g_C + Cb + (size_t)(sb*64)*NN + jt*64, NN, BufB, tid);
        __syncthreads();
        mm64_sub(BufA, BufB, acc, ty4, tx4); // acc -= G @ C
    }

    const float scale = 0.125f;  // 64^-0.5
    float* dst = g_S + Cb + (size_t)(tt*64)*NN + jt*64;
    #pragma unroll
    for (int i = 0; i < 4; i++) {
        float v[4];
        #pragma unroll
        for (int j = 0; j < 4; j++) {
            int r = ty4 + i, c = tx4 + j;
            int gt = tt*64 + r, gj = jt*64 + c;
            v[j] = (gj <= gt) ? acc[i][j]*scale + FcT[r] - FcJ[c] : -INFINITY;
        }
        *(float4*)(dst + (size_t)(ty4+i)*NN + tx4) = make_float4(v[0],v[1],v[2],v[3]);
    }
}

// ---------------- causal softmax (rows of the written region only) -----------
__global__ void softmax_k() {
    int t = blockIdx.x, bh = blockIdx.y;
    int jmax = ((t >> 6) + 1) << 6;
    float* row = g_S + (size_t)bh*NN*NN + (size_t)t*NN;
    __shared__ float red[256];
    int tid = threadIdx.x;
    float m = -INFINITY;
    for (int j = tid; j < jmax; j += 256) m = fmaxf(m, row[j]);
    red[tid] = m; __syncthreads();
    for (int o = 128; o; o >>= 1) { if (tid < o) red[tid] = fmaxf(red[tid], red[tid+o]); __syncthreads(); }
    m = red[0]; __syncthreads();
    float s = 0.f;
    for (int j = tid; j < jmax; j += 256) { float e = expf(row[j] - m); row[j] = e; s += e; }
    red[tid] = s; __syncthreads();
    for (int o = 128; o; o >>= 1) { if (tid < o) red[tid] += red[tid+o]; __syncthreads(); }
    float inv = 1.f / red[0];
    for (int j = tid; j < jmax; j += 256) row[j] *= inv;
}

// ---------------- O_h = P @ V_h (causal tiles only) --------------------------
__global__ void pv_k() {
    int tm = blockIdx.x, bh = blockIdx.y;
    int b = bh / HH, h = bh % HH;
    extern __shared__ float sm[];
    float* Ps = sm;          // Ps[jj][r]
    float* Vs = sm + TSZ;    // Vs[jj][dd]
    int tid = threadIdx.x, tx4 = (tid & 15)*4, ty4 = (tid >> 4)*4;
    float acc[4][4] = {};
    for (int jt = 0; jt <= tm; jt++) {
        __syncthreads();
        load_T (g_S + (size_t)bh*NN*NN + (size_t)(tm*64)*NN + jt*64, NN, Ps, tid);
        load_f4(g_v + (size_t)(b*NN + jt*64)*DD + h*HD, DD, Vs, tid);
        __syncthreads();
        mm64_add(Ps, Vs, acc, ty4, tx4);
    }
    float* dst = g_O + (size_t)(b*NN + tm*64)*DD + h*HD;
    #pragma unroll
    for (int i = 0; i < 4; i++) {
        float4 o = make_float4(acc[i][0], acc[i][1], acc[i][2], acc[i][3]);
        *(float4*)(dst + (size_t)(ty4+i)*DD + tx4) = o;
    }
}

// -----------------------------------------------------------------------------
extern "C" void kernel_launch(void* const* d_in, const int* in_sizes, int n_in,
                              void* d_out, int out_size) {
    const float* x     = (const float*)d_in[0];
    const float* Wq    = (const float*)d_in[1];
    const float* Wk    = (const float*)d_in[2];
    const float* Wv    = (const float*)d_in[3];
    const float* Wo    = (const float*)d_in[4];
    const float* Ww1   = (const float*)d_in[5];
    const float* Ww2   = (const float*)d_in[6];
    const float* Wb    = (const float*)d_in[7];
    const float* Wf    = (const float*)d_in[8];
    const float* delta = (const float*)d_in[9];
    float* out = (float*)d_out;

    static bool attr_done = false;
    if (!attr_done) {
        cudaFuncSetAttribute(proj_small_k, cudaFuncAttributeMaxDynamicSharedMemorySize, (128*65 + 128*100)*4);
        cudaFuncSetAttribute(sgemm64_k,    cudaFuncAttributeMaxDynamicSharedMemorySize, 2*TSZ*4);
        cudaFuncSetAttribute(pre_k,        cudaFuncAttributeMaxDynamicSharedMemorySize, 2*TSZ*4);
        cudaFuncSetAttribute(solve2_k,     cudaFuncAttributeMaxDynamicSharedMemorySize, 2*TSZ*4);
        cudaFuncSetAttribute(scores2_k,    cudaFuncAttributeMaxDynamicSharedMemorySize, 3*TSZ*4);
        cudaFuncSetAttribute(pv_k,         cudaFuncAttributeMaxDynamicSharedMemorySize, 2*TSZ*4);
        attr_done = true;
    }

    float *pq, *pk, *pv, *pw, *pw1, *pO;
    cudaGetSymbolAddress((void**)&pq,  g_q);
    cudaGetSymbolAddress((void**)&pk,  g_k);
    cudaGetSymbolAddress((void**)&pv,  g_v);
    cudaGetSymbolAddress((void**)&pw,  g_w);
    cudaGetSymbolAddress((void**)&pw1, g_w1);
    cudaGetSymbolAddress((void**)&pO,  g_O);
    float *pC, *pL, *pG;
    cudaGetSymbolAddress((void**)&pC, g_C);
    cudaGetSymbolAddress((void**)&pL, g_L);
    cudaGetSymbolAddress((void**)&pG, g_G);

    const int M = BB*NN;   // 2048
    dim3 blk(256);
    dim3 gfull(M/64, DD/64);           // 32 x 16
    size_t smem2 = 2*TSZ*sizeof(float);
    size_t smem3 = 3*TSZ*sizeof(float);

    // big projections
    sgemm64_k<<<gfull, blk, smem2>>>(x, Wq, pq, DD, DD, DD, DD);
    sgemm64_k<<<gfull, blk, smem2>>>(x, Wk, pk, DD, DD, DD, DD);
    sgemm64_k<<<gfull, blk, smem2>>>(x, Wv, pv, DD, DD, DD, DD);

    // fused skinny projections (w1 | xb | xf), split-K + reduce
    proj_small_k<<<dim3(M/64, 8), blk, (128*65 + 128*100)*4>>>(x, Ww1, Wb, Wf);
    proj_small_reduce_k<<<(2048*96 + 255)/256, 256>>>();

    // w = w1 @ Ww2  (K=64)
    sgemm64_k<<<gfull, blk, smem2>>>(pw1, Ww2, pw, HD, HD, DD, DD);

    // w normalize, gates, decay cumsum
    normw_k<<<(BB*NN*HH*32)/256, 256>>>();
    gates_k<<<(BB*NN*HH + 255)/256, 256>>>(delta);
    cumsum_k<<<BH, NN>>>();

    // precompute RHS (normal), L (transposed), G (transposed)
    dim3 gpre(NTRI, BH);
    pre_k<<<gpre, blk, smem2>>>(pw, pk, pC, /*diagKeepEq=*/0, /*useBeta=*/0, /*storeT=*/0);
    pre_k<<<gpre, blk, smem2>>>(pw, pw, pL, /*diagKeepEq=*/0, /*useBeta=*/1, /*storeT=*/1);
    pre_k<<<gpre, blk, smem2>>>(pq, pw, pG, /*diagKeepEq=*/1, /*useBeta=*/1, /*storeT=*/1);

    // blocked UT triangular solve: 16 sequential block-row steps
    for (int ib = 0; ib < NT; ib++)
        solve2_k<<<dim3(ib + 1, BH), blk, smem2>>>(ib);

    // logits, softmax, P@V, output projection
    scores2_k<<<dim3(NTRI, BH), blk, smem3>>>();
    softmax_k<<<dim3(NN, BH), 256>>>();
    pv_k<<<dim3(NT, BH), blk, smem2>>>();
    sgemm64_k<<<gfull, blk, smem2>>>(pO, Wo, out, DD, DD, DD, DD);
}

// round 8
// speedup vs baseline: 2.1739x; 1.1276x over previous
#include <cuda_runtime.h>
#include <cuda_bf16.h>
#include <math.h>
#include <stdint.h>

#define BB 2
#define NN 1024
#define DD 1024
#define HH 16
#define HD 64
#define BH (BB*HH)     // 32
#define NT (NN/64)     // 16
#define NTRI (NT*(NT+1)/2)   // 136
#define TP 72          // smem tile pitch (floats): 8qc+qr bank pattern, conflict-free frags
#define TSZ (64*TP)    // 4608 floats = 18432 bytes per tile

// ---------------- scratch (device globals; no allocation allowed) -------------
__device__ float g_q[BB*NN*DD];
__device__ float g_k[BB*NN*DD];
__device__ float g_v[BB*NN*DD];
__device__ float g_w[BB*NN*DD];
__device__ float g_w1[BB*NN*HD];
__device__ float g_xb[BB*NN*HH];
__device__ float g_xf[BB*NN*HH];
__device__ float g_beta[BH*NN];
__device__ float g_Fc[BH*NN];
__device__ float g_C[(size_t)BH*NN*NN];   // RHS -> solved C in place (normal layout)
__device__ float g_L[(size_t)BH*NN*NN];   // L stored TRANSPOSED: g_L[s*NN+r] = L[r][s]
__device__ float g_G[(size_t)BH*NN*NN];   // G stored TRANSPOSED: g_G[s*NN+t] = G[t][s]
__device__ float g_S[(size_t)BH*NN*NN];   // logits -> P in place
__device__ float g_O[BB*NN*DD];
__device__ float g_part[8*2048*96];       // split-K partials for skinny projections

// ---------------- tile loaders: 64x64, 256 threads ---------------------------
__device__ __forceinline__ void load_f4(const float* __restrict__ g, int ldg,
                                        float* __restrict__ s, int tid) {
    #pragma unroll
    for (int v = 0; v < 4; v++) {
        int e = tid + v*256;
        int r = e >> 4, c4 = e & 15;
        float4 val = *(const float4*)(g + (size_t)r*ldg + c4*4);
        *(float4*)(s + r*TP + c4*4) = val;
    }
}
__device__ __forceinline__ void load_T(const float* __restrict__ g, int ldg,
                                       float* __restrict__ s, int tid) {
    #pragma unroll
    for (int v = 0; v < 4; v++) {
        int e = tid + v*256;
        int r = e >> 4, c4 = e & 15;
        float4 val = *(const float4*)(g + (size_t)r*ldg + c4*4);
        s[(c4*4+0)*TP + r] = val.x;
        s[(c4*4+1)*TP + r] = val.y;
        s[(c4*4+2)*TP + r] = val.z;
        s[(c4*4+3)*TP + r] = val.w;
    }
}

// ---------------- tf32 split-mma machinery -----------------------------------
__device__ __forceinline__ void split_tf32(float x, uint32_t& hi, uint32_t& lo) {
    uint32_t u = __float_as_uint(x);
    uint32_t h = u & 0xFFFFE000u;           // truncate to tf32 mantissa (exact residual)
    hi = h;
    lo = __float_as_uint(x - __uint_as_float(h));
}
__device__ __forceinline__ void mma_tf32(float (&c)[4],
                                         uint32_t a0, uint32_t a1, uint32_t a2, uint32_t a3,
                                         uint32_t b0, uint32_t b1) {
    asm volatile("mma.sync.aligned.m16n8k8.row.col.f32.tf32.tf32.f32 "
        "{%0,%1,%2,%3}, {%4,%5,%6,%7}, {%8,%9}, {%0,%1,%2,%3};\n"
        : "+f"(c[0]), "+f"(c[1]), "+f"(c[2]), "+f"(c[3])
        : "r"(a0), "r"(a1), "r"(a2), "r"(a3), "r"(b0), "r"(b1));
}

// warp-cooperative 64x64x64: acc (+/-)= A @ B over smem tiles As[k*TP+m], Bs[k*TP+n].
// 8 warps: wm = warp>>2 (0..1) covers 32 m-rows, wn = warp&3 (0..3) covers 16 n-cols.
// acc[mi][ni][e]: row = wm*32+mi*16 + (lane>>2) + (e>=2?8:0)
//                 col = wn*16+ni*8  + 2*(lane&3) + (e&1)
__device__ __forceinline__ void wmm64(const float* __restrict__ As,
                                      const float* __restrict__ Bs,
                                      float (&acc)[2][2][4],
                                      int wm, int wn, int lane, bool neg) {
    int qr = lane >> 2, qc = lane & 3;
    #pragma unroll
    for (int ks = 0; ks < 8; ks++) {
        int k0 = ks*8;
        uint32_t ah[2][4], al[2][4];
        #pragma unroll
        for (int mi = 0; mi < 2; mi++) {
            int m0 = wm*32 + mi*16 + qr;
            split_tf32(As[(k0+qc  )*TP + m0    ], ah[mi][0], al[mi][0]);
            split_tf32(As[(k0+qc  )*TP + m0 + 8], ah[mi][1], al[mi][1]);
            split_tf32(As[(k0+qc+4)*TP + m0    ], ah[mi][2], al[mi][2]);
            split_tf32(As[(k0+qc+4)*TP + m0 + 8], ah[mi][3], al[mi][3]);
        }
        uint32_t bh[2][2], bl[2][2];
        #pragma unroll
        for (int ni = 0; ni < 2; ni++) {
            int nn = wn*16 + ni*8 + qr;
            float y0 = Bs[(k0+qc  )*TP + nn];
            float y1 = Bs[(k0+qc+4)*TP + nn];
            if (neg) { y0 = -y0; y1 = -y1; }
            split_tf32(y0, bh[ni][0], bl[ni][0]);
            split_tf32(y1, bh[ni][1], bl[ni][1]);
        }
        #pragma unroll
        for (int mi = 0; mi < 2; mi++)
            #pragma unroll
            for (int ni = 0; ni < 2; ni++) {
                mma_tf32(acc[mi][ni], ah[mi][0],ah[mi][1],ah[mi][2],ah[mi][3], bh[ni][0],bh[ni][1]);
                mma_tf32(acc[mi][ni], ah[mi][0],ah[mi][1],ah[mi][2],ah[mi][3], bl[ni][0],bl[ni][1]);
                mma_tf32(acc[mi][ni], al[mi][0],al[mi][1],al[mi][2],al[mi][3], bh[ni][0],bh[ni][1]);
            }
    }
}

// triangular block index decode
__device__ __forceinline__ void tri_decode(int t, int& ti, int& tj) {
    int i = (int)((sqrtf(8.f*t + 1.f) - 1.f) * 0.5f);
    while ((i+1)*(i+2)/2 <= t) i++;
    while (i*(i+1)/2 > t) i--;
    ti = i; tj = t - i*(i+1)/2;
}

// ---------------- big SGEMM: C = A @ B, all dims multiples of 64 -------------
__global__ void sgemm64_k(const float* __restrict__ A, const float* __restrict__ B,
                          float* __restrict__ C, int K,
                          int lda, int ldb, int ldc) {
    extern __shared__ float sm[];
    float* As = sm;
    float* Bs = sm + TSZ;
    int tid = threadIdx.x;
    int warp = tid >> 5, lane = tid & 31;
    int wm = warp >> 2, wn = warp & 3;
    int qr = lane >> 2, qc = lane & 3;
    int bm0 = blockIdx.x * 64, bn0 = blockIdx.y * 64;
    float acc[2][2][4] = {};
    for (int k0 = 0; k0 < K; k0 += 64) {
        load_T (A + (size_t)bm0*lda + k0, lda, As, tid);
        load_f4(B + (size_t)k0*ldb + bn0, ldb, Bs, tid);
        __syncthreads();
        wmm64(As, Bs, acc, wm, wn, lane, false);
        __syncthreads();
    }
    #pragma unroll
    for (int mi = 0; mi < 2; mi++)
        #pragma unroll
        for (int ni = 0; ni < 2; ni++) {
            int r0 = bm0 + wm*32 + mi*16 + qr;
            int c0 = bn0 + wn*16 + ni*8 + 2*qc;
            *(float2*)(C + (size_t)r0*ldc + c0)     = make_float2(acc[mi][ni][0], acc[mi][ni][1]);
            *(float2*)(C + (size_t)(r0+8)*ldc + c0) = make_float2(acc[mi][ni][2], acc[mi][ni][3]);
        }
}

// ------------- fused skinny projections: x @ [Ww1 | Wb | Wf], split-K --------
__global__ void proj_small_k(const float* __restrict__ x,
                             const float* __restrict__ Ww1,
                             const float* __restrict__ Wb,
                             const float* __restrict__ Wf) {
    extern __shared__ float sm[];
    float* As = sm;            // [128][65]
    float* Bs = sm + 128*65;   // [128][100]
    int mt = blockIdx.x, kc = blockIdx.y;
    int tid = threadIdx.x, tx = tid & 15, ty = tid >> 4;
    int m0 = mt*64, k0 = kc*128;
    for (int i = tid; i < 64*128; i += 256) {
        int m = i >> 7, kk = i & 127;
        As[kk*65 + m] = x[(size_t)(m0+m)*DD + k0 + kk];
    }
    for (int i = tid; i < 128*96; i += 256) {
        int kk = i / 96, c = i - kk*96;
        int kg = k0 + kk;
        float v;
        if (c < 64)      v = Ww1[kg*64 + c];
        else if (c < 80) v = Wb[kg*16 + (c-64)];
        else             v = Wf[kg*16 + (c-80)];
        Bs[kk*100 + c] = v;
    }
    __syncthreads();
    float acc[4][6] = {};
    #pragma unroll 8
    for (int kk = 0; kk < 128; kk++) {
        float a[4], b[6];
        #pragma unroll
        for (int i = 0; i < 4; i++) a[i] = As[kk*65 + ty*4 + i];
        #pragma unroll
        for (int j = 0; j < 6; j++) b[j] = Bs[kk*100 + tx*6 + j];
        #pragma unroll
        for (int i = 0; i < 4; i++)
            #pragma unroll
            for (int j = 0; j < 6; j++) acc[i][j] = fmaf(a[i], b[j], acc[i][j]);
    }
    float* dst = g_part + ((size_t)kc*2048 + m0)*96;
    #pragma unroll
    for (int i = 0; i < 4; i++)
        #pragma unroll
        for (int j = 0; j < 6; j++)
            dst[(size_t)(ty*4+i)*96 + tx*6 + j] = acc[i][j];
}
__global__ void proj_small_reduce_k() {
    int idx = blockIdx.x*256 + threadIdx.x;
    if (idx >= 2048*96) return;
    float s = 0.f;
    #pragma unroll
    for (int kc = 0; kc < 8; kc++) s += g_part[(size_t)kc*2048*96 + idx];
    int row = idx / 96, c = idx - (idx/96)*96;
    if (c < 64)      g_w1[row*64 + c] = s;
    else if (c < 80) g_xb[row*16 + (c-64)] = s;
    else             g_xf[row*16 + (c-80)] = s;
}

// ---------------- l2-normalize w per (b,t,h) over hd=64 ----------------------
__global__ void normw_k() {
    int wid = (blockIdx.x * blockDim.x + threadIdx.x) >> 5;
    int lane = threadIdx.x & 31;
    if (wid >= BB*NN*HH) return;
    int h = wid % HH;
    int t = (wid / HH) % NN;
    int b = wid / (HH*NN);
    float* base = g_w + (size_t)(b*NN + t)*DD + h*HD;
    float v0 = base[lane], v1 = base[lane+32];
    float ss = v0*v0 + v1*v1;
    #pragma unroll
    for (int o = 16; o; o >>= 1) ss += __shfl_xor_sync(0xffffffffu, ss, o);
    float r = rsqrtf(ss + 1e-6f);
    base[lane] = v0*r; base[lane+32] = v1*r;
}

// ---------------- beta = 2*sigmoid(x@Wb); logf = logsigmoid(x@Wf + delta) ----
__global__ void gates_k(const float* __restrict__ delta) {
    int idx = blockIdx.x * blockDim.x + threadIdx.x;
    if (idx >= BB*NN*HH) return;
    int h = idx % HH;
    int t = (idx / HH) % NN;
    int b = idx / (HH*NN);
    float xb = g_xb[idx];
    float beta = 2.f / (1.f + expf(-xb));
    float z = g_xf[idx] + delta[h];
    float lf = fminf(z, 0.f) - log1pf(expf(-fabsf(z)));
    int bh = b*HH + h;
    g_beta[bh*NN + t] = beta;
    g_Fc[bh*NN + t] = lf;
}

// inclusive scan over n per (b,h)
__global__ void cumsum_k() {
    __shared__ float buf[NN];
    int bh = blockIdx.x, t = threadIdx.x;
    buf[t] = g_Fc[bh*NN + t];
    __syncthreads();
    for (int o = 1; o < NN; o <<= 1) {
        float add = (t >= o) ? buf[t - o] : 0.f;
        __syncthreads();
        buf[t] += add;
        __syncthreads();
    }
    g_Fc[bh*NN + t] = buf[t];
}

// ------------- precompute masked rank-64 tile products -----------------------
__global__ void pre_k(const float* __restrict__ Abase, const float* __restrict__ Bbase,
                      float* __restrict__ Out, int diagKeepEq, int useBeta, int storeT) {
    int ti, tj; tri_decode(blockIdx.x, ti, tj);
    int bh = blockIdx.y;
    extern __shared__ float sm[];
    float* As = sm; float* Bs = sm + TSZ;
    __shared__ float betaS[64];
    int b = bh / HH, h = bh % HH;
    int tid = threadIdx.x;
    int warp = tid >> 5, lane = tid & 31;
    int wm = warp >> 2, wn = warp & 3;
    int qr = lane >> 2, qc = lane & 3;
    size_t xbase = (size_t)b*NN*DD + (size_t)h*HD;
    load_T(Abase + xbase + (size_t)(ti*64)*DD, DD, As, tid);   // As[d][r]
    load_T(Bbase + xbase + (size_t)(tj*64)*DD, DD, Bs, tid);   // Bs[d][c]
    if (tid < 64) betaS[tid] = useBeta ? g_beta[bh*NN + tj*64 + tid] : 1.f;
    __syncthreads();
    bool diag = (ti == tj);
    float acc[2][2][4] = {};
    if (!storeT) {
        wmm64(As, Bs, acc, wm, wn, lane, false);     // element (rp, cp) = P[rp][cp]
        float* dst = Out + (size_t)bh*NN*NN + (size_t)(ti*64)*NN + tj*64;
        #pragma unroll
        for (int mi = 0; mi < 2; mi++)
            #pragma unroll
            for (int ni = 0; ni < 2; ni++)
                #pragma unroll
                for (int e = 0; e < 4; e++) {
                    int r = wm*32 + mi*16 + qr + ((e>=2)?8:0);
                    int c = wn*16 + ni*8 + 2*qc + (e&1);
                    float x = acc[mi][ni][e] * betaS[c];
                    if (diag && (diagKeepEq ? (c > r) : (c >= r))) x = 0.f;
                    dst[(size_t)r*NN + c] = x;
                }
    } else {
        wmm64(Bs, As, acc, wm, wn, lane, false);     // element (rp, cp) = P[cp][rp] : rp=c_orig, cp=r_orig
        float* dst = Out + (size_t)bh*NN*NN + (size_t)(tj*64)*NN + ti*64;
        #pragma unroll
        for (int mi = 0; mi < 2; mi++)
            #pragma unroll
            for (int ni = 0; ni < 2; ni++)
                #pragma unroll
                for (int e = 0; e < 4; e++) {
                    int rp = wm*32 + mi*16 + qr + ((e>=2)?8:0);   // original column
                    int cp = wn*16 + ni*8 + 2*qc + (e&1);         // original row
                    float x = acc[mi][ni][e] * betaS[rp];
                    if (diag && (diagKeepEq ? (rp > cp) : (rp >= cp))) x = 0.f;
                    dst[(size_t)rp*NN + cp] = x;
                }
    }
}

// ---------------- blocked unit-lower triangular solve ------------------------
// C[ib][ct] = (I+L_ii)^{-1} ( C[ib][ct] - sum_{ct<=j<ib} L[ib][j] C[j][ct] )
__global__ void solve2_k(int ib) {
    int ct = blockIdx.x, bh = blockIdx.y;
    extern __shared__ float sm[];
    float* Ls  = sm;
    float* Css = sm + TSZ;
    int tid = threadIdx.x;
    int warp = tid >> 5, lane = tid & 31;
    int wm = warp >> 2, wn = warp & 3;
    int qr = lane >> 2, qc = lane & 3;
    size_t Cb = (size_t)bh*NN*NN;
    const float* rhs = g_C + Cb + (size_t)(ib*64)*NN + ct*64;
    float acc[2][2][4];
    #pragma unroll
    for (int mi = 0; mi < 2; mi++)
        #pragma unroll
        for (int ni = 0; ni < 2; ni++) {
            int r0 = wm*32 + mi*16 + qr;
            int c0 = wn*16 + ni*8 + 2*qc;
            float2 v0 = *(const float2*)(rhs + (size_t)r0*NN + c0);
            float2 v1 = *(const float2*)(rhs + (size_t)(r0+8)*NN + c0);
            acc[mi][ni][0] = v0.x; acc[mi][ni][1] = v0.y;
            acc[mi][ni][2] = v1.x; acc[mi][ni][3] = v1.y;
        }

    for (int j = ct; j < ib; j++) {
        __syncthreads();
        load_f4(g_L + Cb + (size_t)(j*64)*NN + ib*64, NN, Ls, tid);   // As[s][r] = L[r][s]
        load_f4(g_C + Cb + (size_t)(j*64)*NN + ct*64, NN, Css, tid);  // Bs[s][c]
        __syncthreads();
        wmm64(Ls, Css, acc, wm, wn, lane, true);
    }

    // diag: x = (I+L_ii)^{-1} acc ; Ls[s][r] = L[r][s]
    __syncthreads();
    load_f4(g_L + Cb + (size_t)(ib*64)*NN + ib*64, NN, Ls, tid);
    #pragma unroll
    for (int mi = 0; mi < 2; mi++)
        #pragma unroll
        for (int ni = 0; ni < 2; ni++)
            #pragma unroll
            for (int e = 0; e < 4; e++) {
                int r = wm*32 + mi*16 + qr + ((e>=2)?8:0);
                int c = wn*16 + ni*8 + 2*qc + (e&1);
                Css[r*TP + c] = acc[mi][ni][e];
            }
    __syncthreads();
    if (tid < 64) {
        int c = tid;
        for (int r = 1; r < 64; r++) {
            float s0 = 0.f, s1 = 0.f, s2 = 0.f, s3 = 0.f;
            int rp = 0;
            for (; rp + 3 < r; rp += 4) {
                s0 += Ls[(rp    )*TP + r] * Css[(rp    )*TP + c];
                s1 += Ls[(rp + 1)*TP + r] * Css[(rp + 1)*TP + c];
                s2 += Ls[(rp + 2)*TP + r] * Css[(rp + 2)*TP + c];
                s3 += Ls[(rp + 3)*TP + r] * Css[(rp + 3)*TP + c];
            }
            for (; rp < r; rp++) s0 += Ls[rp*TP + r] * Css[rp*TP + c];
            Css[r*TP + c] -= (s0 + s1) + (s2 + s3);
        }
    }
    __syncthreads();
    float* dst = g_C + Cb + (size_t)(ib*64)*NN + ct*64;
    for (int i = tid; i < 1024; i += 256) {          // 64x64 via float4
        int r = i >> 4, c4 = i & 15;
        float4 o = make_float4(Css[r*TP + c4*4], Css[r*TP + c4*4+1],
                               Css[r*TP + c4*4+2], Css[r*TP + c4*4+3]);
        *(float4*)(dst + (size_t)r*NN + c4*4) = o;
    }
}

// ---------------- logits: S = QK^T - G @ C, + decay, mask --------------------
__global__ void scores2_k() {
    int tt, jt; tri_decode(blockIdx.x, tt, jt);
    int bh = blockIdx.y;
    extern __shared__ float sm[];
    float* Qst  = sm;
    float* BufA = sm + TSZ;
    float* BufB = sm + 2*TSZ;
    __shared__ float FcT[64], FcJ[64];
    int b = bh / HH, h = bh % HH;
    int tid = threadIdx.x;
    int warp = tid >> 5, lane = tid & 31;
    int wm = warp >> 2, wn = warp & 3;
    int qr = lane >> 2, qc = lane & 3;
    size_t xbase = (size_t)b*NN*DD + (size_t)h*HD;
    size_t Cb = (size_t)bh*NN*NN;

    load_T(g_q + xbase + (size_t)(tt*64)*DD, DD, Qst, tid);
    load_T(g_k + xbase + (size_t)(jt*64)*DD, DD, BufA, tid);
    if (tid < 64) {
        FcT[tid] = g_Fc[bh*NN + tt*64 + tid];
        FcJ[tid] = g_Fc[bh*NN + jt*64 + tid];
    }
    __syncthreads();

    float acc[2][2][4] = {};
    wmm64(Qst, BufA, acc, wm, wn, lane, false);       // Q K^T

    for (int sb = jt; sb <= tt; sb++) {
        __syncthreads();
        load_f4(g_G + Cb + (size_t)(sb*64)*NN + tt*64, NN, BufA, tid);  // As[s][r] = G[r][s]
        load_f4(g_C + Cb + (size_t)(sb*64)*NN + jt*64, NN, BufB, tid);  // Bs[s][c]
        __syncthreads();
        wmm64(BufA, BufB, acc, wm, wn, lane, true);    // acc -= G @ C
    }

    const float scale = 0.125f;
    float* dst = g_S + Cb + (size_t)(tt*64)*NN + jt*64;
    #pragma unroll
    for (int mi = 0; mi < 2; mi++)
        #pragma unroll
        for (int ni = 0; ni < 2; ni++)
            #pragma unroll
            for (int e = 0; e < 4; e++) {
                int r = wm*32 + mi*16 + qr + ((e>=2)?8:0);
                int c = wn*16 + ni*8 + 2*qc + (e&1);
                int gt = tt*64 + r, gj = jt*64 + c;
                float v = (gj <= gt) ? acc[mi][ni][e]*scale + FcT[r] - FcJ[c] : -INFINITY;
                dst[(size_t)r*NN + c] = v;
            }
}

// ---------------- causal softmax ---------------------------------------------
__global__ void softmax_k() {
    int t = blockIdx.x, bh = blockIdx.y;
    int jmax = ((t >> 6) + 1) << 6;
    float* row = g_S + (size_t)bh*NN*NN + (size_t)t*NN;
    __shared__ float red[256];
    int tid = threadIdx.x;
    float m = -INFINITY;
    for (int j = tid; j < jmax; j += 256) m = fmaxf(m, row[j]);
    red[tid] = m; __syncthreads();
    for (int o = 128; o; o >>= 1) { if (tid < o) red[tid] = fmaxf(red[tid], red[tid+o]); __syncthreads(); }
    m = red[0]; __syncthreads();
    float s = 0.f;
    for (int j = tid; j < jmax; j += 256) { float e = expf(row[j] - m); row[j] = e; s += e; }
    red[tid] = s; __syncthreads();
    for (int o = 128; o; o >>= 1) { if (tid < o) red[tid] += red[tid+o]; __syncthreads(); }
    float inv = 1.f / red[0];
    for (int j = tid; j < jmax; j += 256) row[j] *= inv;
}

// ---------------- O_h = P @ V_h (causal tiles only) --------------------------
__global__ void pv_k() {
    int tm = blockIdx.x, bh = blockIdx.y;
    int b = bh / HH, h = bh % HH;
    extern __shared__ float sm[];
    float* Ps = sm;          // Ps[jj][r]
    float* Vs = sm + TSZ;    // Vs[jj][dd]
    int tid = threadIdx.x;
    int warp = tid >> 5, lane = tid & 31;
    int wm = warp >> 2, wn = warp & 3;
    int qr = lane >> 2, qc = lane & 3;
    float acc[2][2][4] = {};
    for (int jt = 0; jt <= tm; jt++) {
        __syncthreads();
        load_T (g_S + (size_t)bh*NN*NN + (size_t)(tm*64)*NN + jt*64, NN, Ps, tid);
        load_f4(g_v + (size_t)(b*NN + jt*64)*DD + h*HD, DD, Vs, tid);
        __syncthreads();
        wmm64(Ps, Vs, acc, wm, wn, lane, false);
    }
    float* dst = g_O + (size_t)(b*NN + tm*64)*DD + h*HD;
    #pragma unroll
    for (int mi = 0; mi < 2; mi++)
        #pragma unroll
        for (int ni = 0; ni < 2; ni++) {
            int r0 = wm*32 + mi*16 + qr;
            int c0 = wn*16 + ni*8 + 2*qc;
            *(float2*)(dst + (size_t)r0*DD + c0)     = make_float2(acc[mi][ni][0], acc[mi][ni][1]);
            *(float2*)(dst + (size_t)(r0+8)*DD + c0) = make_float2(acc[mi][ni][2], acc[mi][ni][3]);
        }
}

// -----------------------------------------------------------------------------
extern "C" void kernel_launch(void* const* d_in, const int* in_sizes, int n_in,
                              void* d_out, int out_size) {
    const float* x     = (const float*)d_in[0];
    const float* Wq    = (const float*)d_in[1];
    const float* Wk    = (const float*)d_in[2];
    const float* Wv    = (const float*)d_in[3];
    const float* Wo    = (const float*)d_in[4];
    const float* Ww1   = (const float*)d_in[5];
    const float* Ww2   = (const float*)d_in[6];
    const float* Wb    = (const float*)d_in[7];
    const float* Wf    = (const float*)d_in[8];
    const float* delta = (const float*)d_in[9];
    float* out = (float*)d_out;

    static bool attr_done = false;
    if (!attr_done) {
        cudaFuncSetAttribute(proj_small_k, cudaFuncAttributeMaxDynamicSharedMemorySize, (128*65 + 128*100)*4);
        cudaFuncSetAttribute(sgemm64_k,    cudaFuncAttributeMaxDynamicSharedMemorySize, 2*TSZ*4);
        cudaFuncSetAttribute(pre_k,        cudaFuncAttributeMaxDynamicSharedMemorySize, 2*TSZ*4);
        cudaFuncSetAttribute(solve2_k,     cudaFuncAttributeMaxDynamicSharedMemorySize, 2*TSZ*4);
        cudaFuncSetAttribute(scores2_k,    cudaFuncAttributeMaxDynamicSharedMemorySize, 3*TSZ*4);
        cudaFuncSetAttribute(pv_k,         cudaFuncAttributeMaxDynamicSharedMemorySize, 2*TSZ*4);
        attr_done = true;
    }

    float *pq, *pk, *pv, *pw, *pw1, *pO;
    cudaGetSymbolAddress((void**)&pq,  g_q);
    cudaGetSymbolAddress((void**)&pk,  g_k);
    cudaGetSymbolAddress((void**)&pv,  g_v);
    cudaGetSymbolAddress((void**)&pw,  g_w);
    cudaGetSymbolAddress((void**)&pw1, g_w1);
    cudaGetSymbolAddress((void**)&pO,  g_O);
    float *pC, *pL, *pG;
    cudaGetSymbolAddress((void**)&pC, g_C);
    cudaGetSymbolAddress((void**)&pL, g_L);
    cudaGetSymbolAddress((void**)&pG, g_G);

    const int M = BB*NN;   // 2048
    dim3 blk(256);
    dim3 gfull(M/64, DD/64);           // 32 x 16
    size_t smem2 = 2*TSZ*sizeof(float);
    size_t smem3 = 3*TSZ*sizeof(float);

    // big projections
    sgemm64_k<<<gfull, blk, smem2>>>(x, Wq, pq, DD, DD, DD, DD);
    sgemm64_k<<<gfull, blk, smem2>>>(x, Wk, pk, DD, DD, DD, DD);
    sgemm64_k<<<gfull, blk, smem2>>>(x, Wv, pv, DD, DD, DD, DD);

    // fused skinny projections (w1 | xb | xf), split-K + reduce
    proj_small_k<<<dim3(M/64, 8), blk, (128*65 + 128*100)*4>>>(x, Ww1, Wb, Wf);
    proj_small_reduce_k<<<(2048*96 + 255)/256, 256>>>();

    // w = w1 @ Ww2  (K=64)
    sgemm64_k<<<gfull, blk, smem2>>>(pw1, Ww2, pw, HD, HD, DD, DD);

    // w normalize, gates, decay cumsum
    normw_k<<<(BB*NN*HH*32)/256, 256>>>();
    gates_k<<<(BB*NN*HH + 255)/256, 256>>>(delta);
    cumsum_k<<<BH, NN>>>();

    // precompute RHS (normal), L (transposed), G (transposed)
    dim3 gpre(NTRI, BH);
    pre_k<<<gpre, blk, smem2>>>(pw, pk, pC, /*diagKeepEq=*/0, /*useBeta=*/0, /*storeT=*/0);
    pre_k<<<gpre, blk, smem2>>>(pw, pw, pL, /*diagKeepEq=*/0, /*useBeta=*/1, /*storeT=*/1);
    pre_k<<<gpre, blk, smem2>>>(pq, pw, pG, /*diagKeepEq=*/1, /*useBeta=*/1, /*storeT=*/1);

    // blocked UT triangular solve: 16 sequential block-row steps
    for (int ib = 0; ib < NT; ib++)
        solve2_k<<<dim3(ib + 1, BH), blk, smem2>>>(ib);

    // logits, softmax, P@V, output projection
    scores2_k<<<dim3(NTRI, BH), blk, smem3>>>();
    softmax_k<<<dim3(NN, BH), 256>>>();
    pv_k<<<dim3(NT, BH), blk, smem2>>>();
    sgemm64_k<<<gfull, blk, smem2>>>(pO, Wo, out, DD, DD, DD, DD);
}

// round 14
// speedup vs baseline: 2.8015x; 1.2887x over previous
#include <cuda_runtime.h>
#include <cuda_bf16.h>
#include <cuda_pipeline.h>
#include <math.h>
#include <stdint.h>

#define BB 2
#define NN 1024
#define DD 1024
#define HH 16
#define HD 64
#define BH (BB*HH)     // 32
#define NT (NN/64)     // 16
#define NTRI (NT*(NT+1)/2)   // 136
#define TP 72          // smem tile pitch (floats): conflict-free for all 4 gather patterns
#define TSZ (64*TP)    // 4608 floats = 18432 bytes per tile

// ---------------- scratch (device globals; no allocation allowed) -------------
__device__ float g_q[BB*NN*DD];
__device__ float g_k[BB*NN*DD];
__device__ float g_v[BB*NN*DD];
__device__ float g_w[BB*NN*DD];
__device__ float g_w1[BB*NN*HD];
__device__ float g_xb[BB*NN*HH];
__device__ float g_xf[BB*NN*HH];
__device__ float g_beta[BH*NN];
__device__ float g_Fc[BH*NN];
__device__ float g_C[(size_t)BH*NN*NN];   // RHS -> solved C in place (normal layout)
__device__ float g_L[(size_t)BH*NN*NN];   // L stored TRANSPOSED: g_L[s*NN+r] = L[r][s]
__device__ float g_G[(size_t)BH*NN*NN];   // G stored TRANSPOSED: g_G[s*NN+t] = G[t][s]
__device__ float g_S[(size_t)BH*NN*NN];   // logits -> P in place
__device__ float g_O[BB*NN*DD];
__device__ float g_part[8*2048*96];       // split-K partials for skinny projections

// ------------- async 64x64 tile copy (row-major, straight) -------------------
__device__ __forceinline__ void cp_tile(const float* __restrict__ g, int ldg,
                                        float* __restrict__ s, int tid) {
    #pragma unroll
    for (int v = 0; v < 4; v++) {
        int e = tid + v*256;
        int r = e >> 4, c4 = e & 15;
        __pipeline_memcpy_async(s + r*TP + c4*4, g + (size_t)r*ldg + c4*4, 16);
    }
}

// ---------------- tf32 split-mma machinery -----------------------------------
__device__ __forceinline__ void split_tf32(float x, uint32_t& hi, uint32_t& lo) {
    uint32_t u = __float_as_uint(x);
    uint32_t h = u & 0xFFFFE000u;
    hi = h;
    lo = __float_as_uint(x - __uint_as_float(h));
}
__device__ __forceinline__ void mma_tf32(float (&c)[4],
                                         uint32_t a0, uint32_t a1, uint32_t a2, uint32_t a3,
                                         uint32_t b0, uint32_t b1) {
    asm volatile("mma.sync.aligned.m16n8k8.row.col.f32.tf32.tf32.f32 "
        "{%0,%1,%2,%3}, {%4,%5,%6,%7}, {%8,%9}, {%0,%1,%2,%3};\n"
        : "+f"(c[0]), "+f"(c[1]), "+f"(c[2]), "+f"(c[3])
        : "r"(a0), "r"(a1), "r"(a2), "r"(a3), "r"(b0), "r"(b1));
}

// warp-cooperative 64x64x64 over smem tiles, layout-parameterized gathering.
// AT=0: As[m*TP+k] ; AT=1: As[k*TP+m]
// BT=0: Bs[k*TP+n] ; BT=1: Bs[n*TP+k]
// acc element: row = wm*32+mi*16 + qr + (e>=2?8:0), col = wn*16+ni*8 + 2*qc + (e&1)
template<int AT, int BT>
__device__ __forceinline__ void wmm64t(const float* __restrict__ As,
                                       const float* __restrict__ Bs,
                                       float (&acc)[2][2][4],
                                       int wm, int wn, int lane, bool neg) {
    int qr = lane >> 2, qc = lane & 3;
    #pragma unroll
    for (int ks = 0; ks < 8; ks++) {
        int k0 = ks*8;
        uint32_t ah[2][4], al[2][4];
        #pragma unroll
        for (int mi = 0; mi < 2; mi++) {
            int m0 = wm*32 + mi*16 + qr;
            float a0, a1, a2, a3;
            if (AT == 0) {
                a0 = As[(m0    )*TP + k0+qc  ];
                a1 = As[(m0 + 8)*TP + k0+qc  ];
                a2 = As[(m0    )*TP + k0+qc+4];
                a3 = As[(m0 + 8)*TP + k0+qc+4];
            } else {
                a0 = As[(k0+qc  )*TP + m0    ];
                a1 = As[(k0+qc  )*TP + m0 + 8];
                a2 = As[(k0+qc+4)*TP + m0    ];
                a3 = As[(k0+qc+4)*TP + m0 + 8];
            }
            split_tf32(a0, ah[mi][0], al[mi][0]);
            split_tf32(a1, ah[mi][1], al[mi][1]);
            split_tf32(a2, ah[mi][2], al[mi][2]);
            split_tf32(a3, ah[mi][3], al[mi][3]);
        }
        uint32_t bh[2][2], bl[2][2];
        #pragma unroll
        for (int ni = 0; ni < 2; ni++) {
            int nn = wn*16 + ni*8 + qr;
            float y0, y1;
            if (BT == 0) {
                y0 = Bs[(k0+qc  )*TP + nn];
                y1 = Bs[(k0+qc+4)*TP + nn];
            } else {
                y0 = Bs[nn*TP + k0+qc  ];
                y1 = Bs[nn*TP + k0+qc+4];
            }
            if (neg) { y0 = -y0; y1 = -y1; }
            split_tf32(y0, bh[ni][0], bl[ni][0]);
            split_tf32(y1, bh[ni][1], bl[ni][1]);
        }
        #pragma unroll
        for (int mi = 0; mi < 2; mi++)
            #pragma unroll
            for (int ni = 0; ni < 2; ni++) {
                mma_tf32(acc[mi][ni], ah[mi][0],ah[mi][1],ah[mi][2],ah[mi][3], bh[ni][0],bh[ni][1]);
                mma_tf32(acc[mi][ni], ah[mi][0],ah[mi][1],ah[mi][2],ah[mi][3], bl[ni][0],bl[ni][1]);
                mma_tf32(acc[mi][ni], al[mi][0],al[mi][1],al[mi][2],al[mi][3], bh[ni][0],bh[ni][1]);
            }
    }
}

// triangular block index decode
__device__ __forceinline__ void tri_decode(int t, int& ti, int& tj) {
    int i = (int)((sqrtf(8.f*t + 1.f) - 1.f) * 0.5f);
    while ((i+1)*(i+2)/2 <= t) i++;
    while (i*(i+1)/2 > t) i--;
    ti = i; tj = t - i*(i+1)/2;
}

// ---------------- big SGEMM: C = A @ B, dims multiples of 64 -----------------
__global__ void sgemm64_k(const float* __restrict__ A, const float* __restrict__ B,
                          float* __restrict__ C, int K,
                          int lda, int ldb, int ldc) {
    extern __shared__ float sm[];
    float* As[2] = {sm,        sm + 2*TSZ};
    float* Bs[2] = {sm + TSZ,  sm + 3*TSZ};
    int tid = threadIdx.x;
    int warp = tid >> 5, lane = tid & 31;
    int wm = warp >> 2, wn = warp & 3;
    int qr = lane >> 2, qc = lane & 3;
    int bm0 = blockIdx.x * 64, bn0 = blockIdx.y * 64;
    int nk = K >> 6;
    cp_tile(A + (size_t)bm0*lda, lda, As[0], tid);
    cp_tile(B + bn0, ldb, Bs[0], tid);
    __pipeline_commit();
    float acc[2][2][4] = {};
    for (int i = 0; i < nk; i++) {
        if (i + 1 < nk) {
            cp_tile(A + (size_t)bm0*lda + (i+1)*64, lda, As[(i+1)&1], tid);
            cp_tile(B + (size_t)((i+1)*64)*ldb + bn0, ldb, Bs[(i+1)&1], tid);
            __pipeline_commit();
        }
        __pipeline_wait_prior((i+1 < nk) ? 1 : 0);
        __syncthreads();
        wmm64t<0,0>(As[i&1], Bs[i&1], acc, wm, wn, lane, false);
        __syncthreads();
    }
    #pragma unroll
    for (int mi = 0; mi < 2; mi++)
        #pragma unroll
        for (int ni = 0; ni < 2; ni++) {
            int r0 = bm0 + wm*32 + mi*16 + qr;
            int c0 = bn0 + wn*16 + ni*8 + 2*qc;
            *(float2*)(C + (size_t)r0*ldc + c0)     = make_float2(acc[mi][ni][0], acc[mi][ni][1]);
            *(float2*)(C + (size_t)(r0+8)*ldc + c0) = make_float2(acc[mi][ni][2], acc[mi][ni][3]);
        }
}

// ------------- fused skinny projections: x @ [Ww1 | Wb | Wf], split-K --------
__global__ void proj_small_k(const float* __restrict__ x,
                             const float* __restrict__ Ww1,
                             const float* __restrict__ Wb,
                             const float* __restrict__ Wf) {
    extern __shared__ float sm[];
    float* As = sm;            // [128][65]
    float* Bs = sm + 128*65;   // [128][100]
    int mt = blockIdx.x, kc = blockIdx.y;
    int tid = threadIdx.x, tx = tid & 15, ty = tid >> 4;
    int m0 = mt*64, k0 = kc*128;
    for (int i = tid; i < 64*128; i += 256) {
        int m = i >> 7, kk = i & 127;
        As[kk*65 + m] = x[(size_t)(m0+m)*DD + k0 + kk];
    }
    for (int i = tid; i < 128*96; i += 256) {
        int kk = i / 96, c = i - kk*96;
        int kg = k0 + kk;
        float v;
        if (c < 64)      v = Ww1[kg*64 + c];
        else if (c < 80) v = Wb[kg*16 + (c-64)];
        else             v = Wf[kg*16 + (c-80)];
        Bs[kk*100 + c] = v;
    }
    __syncthreads();
    float acc[4][6] = {};
    #pragma unroll 8
    for (int kk = 0; kk < 128; kk++) {
        float a[4], b[6];
        #pragma unroll
        for (int i = 0; i < 4; i++) a[i] = As[kk*65 + ty*4 + i];
        #pragma unroll
        for (int j = 0; j < 6; j++) b[j] = Bs[kk*100 + tx*6 + j];
        #pragma unroll
        for (int i = 0; i < 4; i++)
            #pragma unroll
            for (int j = 0; j < 6; j++) acc[i][j] = fmaf(a[i], b[j], acc[i][j]);
    }
    float* dst = g_part + ((size_t)kc*2048 + m0)*96;
    #pragma unroll
    for (int i = 0; i < 4; i++)
        #pragma unroll
        for (int j = 0; j < 6; j++)
            dst[(size_t)(ty*4+i)*96 + tx*6 + j] = acc[i][j];
}
__global__ void proj_small_reduce_k() {
    int idx = blockIdx.x*256 + threadIdx.x;
    if (idx >= 2048*96) return;
    float s = 0.f;
    #pragma unroll
    for (int kc = 0; kc < 8; kc++) s += g_part[(size_t)kc*2048*96 + idx];
    int row = idx / 96, c = idx - (idx/96)*96;
    if (c < 64)      g_w1[row*64 + c] = s;
    else if (c < 80) g_xb[row*16 + (c-64)] = s;
    else             g_xf[row*16 + (c-80)] = s;
}

// ---------------- l2-normalize w per (b,t,h) over hd=64 ----------------------
__global__ void normw_k() {
    int wid = (blockIdx.x * blockDim.x + threadIdx.x) >> 5;
    int lane = threadIdx.x & 31;
    if (wid >= BB*NN*HH) return;
    int h = wid % HH;
    int t = (wid / HH) % NN;
    int b = wid / (HH*NN);
    float* base = g_w + (size_t)(b*NN + t)*DD + h*HD;
    float v0 = base[lane], v1 = base[lane+32];
    float ss = v0*v0 + v1*v1;
    #pragma unroll
    for (int o = 16; o; o >>= 1) ss += __shfl_xor_sync(0xffffffffu, ss, o);
    float r = rsqrtf(ss + 1e-6f);
    base[lane] = v0*r; base[lane+32] = v1*r;
}

// ---------------- beta = 2*sigmoid(x@Wb); logf = logsigmoid(x@Wf + delta) ----
__global__ void gates_k(const float* __restrict__ delta) {
    int idx = blockIdx.x * blockDim.x + threadIdx.x;
    if (idx >= BB*NN*HH) return;
    int h = idx % HH;
    int t = (idx / HH) % NN;
    int b = idx / (HH*NN);
    float xb = g_xb[idx];
    float beta = 2.f / (1.f + expf(-xb));
    float z = g_xf[idx] + delta[h];
    float lf = fminf(z, 0.f) - log1pf(expf(-fabsf(z)));
    int bh = b*HH + h;
    g_beta[bh*NN + t] = beta;
    g_Fc[bh*NN + t] = lf;
}

// inclusive scan over n per (b,h)
__global__ void cumsum_k() {
    __shared__ float buf[NN];
    int bh = blockIdx.x, t = threadIdx.x;
    buf[t] = g_Fc[bh*NN + t];
    __syncthreads();
    for (int o = 1; o < NN; o <<= 1) {
        float add = (t >= o) ? buf[t - o] : 0.f;
        __syncthreads();
        buf[t] += add;
        __syncthreads();
    }
    g_Fc[bh*NN + t] = buf[t];
}

// ------------- precompute masked rank-64 tile products -----------------------
__global__ void pre_k(const float* __restrict__ Abase, const float* __restrict__ Bbase,
                      float* __restrict__ Out, int diagKeepEq, int useBeta, int storeT) {
    int ti, tj; tri_decode(blockIdx.x, ti, tj);
    int bh = blockIdx.y;
    extern __shared__ float sm[];
    float* As = sm; float* Bs = sm + TSZ;
    __shared__ float betaS[64];
    int b = bh / HH, h = bh % HH;
    int tid = threadIdx.x;
    int warp = tid >> 5, lane = tid & 31;
    int wm = warp >> 2, wn = warp & 3;
    int qr = lane >> 2, qc = lane & 3;
    size_t xbase = (size_t)b*NN*DD + (size_t)h*HD;
    cp_tile(Abase + xbase + (size_t)(ti*64)*DD, DD, As, tid);   // [r][d]
    cp_tile(Bbase + xbase + (size_t)(tj*64)*DD, DD, Bs, tid);   // [c][d]
    __pipeline_commit();
    if (tid < 64) betaS[tid] = useBeta ? g_beta[bh*NN + tj*64 + tid] : 1.f;
    __pipeline_wait_prior(0);
    __syncthreads();
    bool diag = (ti == tj);
    float acc[2][2][4] = {};
    if (!storeT) {
        wmm64t<0,1>(As, Bs, acc, wm, wn, lane, false);   // P[r][c]
        float* dst = Out + (size_t)bh*NN*NN + (size_t)(ti*64)*NN + tj*64;
        #pragma unroll
        for (int mi = 0; mi < 2; mi++)
            #pragma unroll
            for (int ni = 0; ni < 2; ni++)
                #pragma unroll
                for (int e = 0; e < 4; e++) {
                    int r = wm*32 + mi*16 + qr + ((e>=2)?8:0);
                    int c = wn*16 + ni*8 + 2*qc + (e&1);
                    float x = acc[mi][ni][e] * betaS[c];
                    if (diag && (diagKeepEq ? (c > r) : (c >= r))) x = 0.f;
                    dst[(size_t)r*NN + c] = x;
                }
    } else {
        wmm64t<0,1>(Bs, As, acc, wm, wn, lane, false);   // element (rp,cp) = P[cp][rp]
        float* dst = Out + (size_t)bh*NN*NN + (size_t)(tj*64)*NN + ti*64;
        #pragma unroll
        for (int mi = 0; mi < 2; mi++)
            #pragma unroll
            for (int ni = 0; ni < 2; ni++)
                #pragma unroll
                for (int e = 0; e < 4; e++) {
                    int rp = wm*32 + mi*16 + qr + ((e>=2)?8:0);   // original column
                    int cp = wn*16 + ni*8 + 2*qc + (e&1);         // original row
                    float x = acc[mi][ni][e] * betaS[rp];
                    if (diag && (diagKeepEq ? (rp > cp) : (rp >= cp))) x = 0.f;
                    dst[(size_t)rp*NN + cp] = x;
                }
    }
}

// ---------------- blocked unit-lower triangular solve ------------------------
// C[ib][ct] = (I+L_ii)^{-1} ( C[ib][ct] - sum_{ct<=j<ib} L[ib][j] C[j][ct] )
__global__ void solve2_k(int ib) {
    int ct = blockIdx.x, bh = blockIdx.y;
    extern __shared__ float sm[];
    float* Ls[2] = {sm,        sm + 2*TSZ};
    float* Cs[2] = {sm + TSZ,  sm + 3*TSZ};
    int tid = threadIdx.x;
    int warp = tid >> 5, lane = tid & 31;
    int wm = warp >> 2, wn = warp & 3;
    int qr = lane >> 2, qc = lane & 3;
    size_t Cb = (size_t)bh*NN*NN;
    const float* rhs = g_C + Cb + (size_t)(ib*64)*NN + ct*64;
    float acc[2][2][4];
    #pragma unroll
    for (int mi = 0; mi < 2; mi++)
        #pragma unroll
        for (int ni = 0; ni < 2; ni++) {
            int r0 = wm*32 + mi*16 + qr;
            int c0 = wn*16 + ni*8 + 2*qc;
            float2 v0 = *(const float2*)(rhs + (size_t)r0*NN + c0);
            float2 v1 = *(const float2*)(rhs + (size_t)(r0+8)*NN + c0);
            acc[mi][ni][0] = v0.x; acc[mi][ni][1] = v0.y;
            acc[mi][ni][2] = v1.x; acc[mi][ni][3] = v1.y;
        }

    int n = ib - ct;
    if (n > 0) {
        cp_tile(g_L + Cb + (size_t)(ct*64)*NN + ib*64, NN, Ls[0], tid);  // [s][r] = L[r][s]
        cp_tile(g_C + Cb + (size_t)(ct*64)*NN + ct*64, NN, Cs[0], tid);  // [s][c]
        __pipeline_commit();
    }
    for (int t = 0; t < n; t++) {
        int j = ct + t;
        if (t + 1 < n) {
            cp_tile(g_L + Cb + (size_t)((j+1)*64)*NN + ib*64, NN, Ls[(t+1)&1], tid);
            cp_tile(g_C + Cb + (size_t)((j+1)*64)*NN + ct*64, NN, Cs[(t+1)&1], tid);
            __pipeline_commit();
        }
        __pipeline_wait_prior((t+1 < n) ? 1 : 0);
        __syncthreads();
        wmm64t<1,0>(Ls[t&1], Cs[t&1], acc, wm, wn, lane, true);
        __syncthreads();
    }

    // diag: x = (I+L_ii)^{-1} acc ; L_ii tile loaded straight: Ls[0][s*TP+r] = L[r][s]
    cp_tile(g_L + Cb + (size_t)(ib*64)*NN + ib*64, NN, Ls[0], tid);
    __pipeline_commit();
    float* Css = Cs[0];
    #pragma unroll
    for (int mi = 0; mi < 2; mi++)
        #pragma unroll
        for (int ni = 0; ni < 2; ni++)
            #pragma unroll
            for (int e = 0; e < 4; e++) {
                int r = wm*32 + mi*16 + qr + ((e>=2)?8:0);
                int c = wn*16 + ni*8 + 2*qc + (e&1);
                Css[r*TP + c] = acc[mi][ni][e];
            }
    __pipeline_wait_prior(0);
    __syncthreads();
    if (tid < 64) {
        int c = tid;
        float* Ld = Ls[0];
        for (int r = 1; r < 64; r++) {
            float s0 = 0.f, s1 = 0.f, s2 = 0.f, s3 = 0.f;
            int rp = 0;
            for (; rp + 3 < r; rp += 4) {
                s0 += Ld[(rp    )*TP + r] * Css[(rp    )*TP + c];
                s1 += Ld[(rp + 1)*TP + r] * Css[(rp + 1)*TP + c];
                s2 += Ld[(rp + 2)*TP + r] * Css[(rp + 2)*TP + c];
                s3 += Ld[(rp + 3)*TP + r] * Css[(rp + 3)*TP + c];
            }
            for (; rp < r; rp++) s0 += Ld[rp*TP + r] * Css[rp*TP + c];
            Css[r*TP + c] -= (s0 + s1) + (s2 + s3);
        }
    }
    __syncthreads();
    float* dst = g_C + Cb + (size_t)(ib*64)*NN + ct*64;
    for (int i = tid; i < 1024; i += 256) {
        int r = i >> 4, c4 = i & 15;
        float4 o = make_float4(Css[r*TP + c4*4], Css[r*TP + c4*4+1],
                               Css[r*TP + c4*4+2], Css[r*TP + c4*4+3]);
        *(float4*)(dst + (size_t)r*NN + c4*4) = o;
    }
}

// ---------------- logits: S = QK^T - G @ C, + decay, mask --------------------
__global__ void scores2_k() {
    int tt, jt; tri_decode(blockIdx.x, tt, jt);
    int bh = blockIdx.y;
    extern __shared__ float sm[];
    float* Qst   = sm;                                  // persistent Q tile [r][d]
    float* tA[2] = {sm + TSZ,   sm + 3*TSZ};
    float* tB[2] = {sm + 2*TSZ, sm + 4*TSZ};
    __shared__ float FcT[64], FcJ[64];
    int b = bh / HH, h = bh % HH;
    int tid = threadIdx.x;
    int warp = tid >> 5, lane = tid & 31;
    int wm = warp >> 2, wn = warp & 3;
    int qr = lane >> 2, qc = lane & 3;
    size_t xbase = (size_t)b*NN*DD + (size_t)h*HD;
    size_t Cb = (size_t)bh*NN*NN;

    cp_tile(g_q + xbase + (size_t)(tt*64)*DD, DD, Qst,   tid);   // [r][d]
    cp_tile(g_k + xbase + (size_t)(jt*64)*DD, DD, tA[0], tid);   // [c][d]
    __pipeline_commit();
    cp_tile(g_G + Cb + (size_t)(jt*64)*NN + tt*64, NN, tA[1], tid);  // [s][r]
    cp_tile(g_C + Cb + (size_t)(jt*64)*NN + jt*64, NN, tB[1], tid);  // [s][c]
    __pipeline_commit();
    if (tid < 64) {
        FcT[tid] = g_Fc[bh*NN + tt*64 + tid];
        FcJ[tid] = g_Fc[bh*NN + jt*64 + tid];
    }
    __pipeline_wait_prior(1);
    __syncthreads();

    float acc[2][2][4] = {};
    wmm64t<0,1>(Qst, tA[0], acc, wm, wn, lane, false);   // Q K^T
    __syncthreads();

    int n = tt - jt + 1;
    for (int t = 0; t < n; t++) {
        int sb = jt + t;
        int cur = (t + 1) & 1;
        if (t + 1 < n) {
            cp_tile(g_G + Cb + (size_t)((sb+1)*64)*NN + tt*64, NN, tA[t&1], tid);
            cp_tile(g_C + Cb + (size_t)((sb+1)*64)*NN + jt*64, NN, tB[t&1], tid);
            __pipeline_commit();
        }
        __pipeline_wait_prior((t+1 < n) ? 1 : 0);
        __syncthreads();
        wmm64t<1,0>(tA[cur], tB[cur], acc, wm, wn, lane, true);   // acc -= G @ C
        __syncthreads();
    }

    const float scale = 0.125f;
    float* dst = g_S + Cb + (size_t)(tt*64)*NN + jt*64;
    #pragma unroll
    for (int mi = 0; mi < 2; mi++)
        #pragma unroll
        for (int ni = 0; ni < 2; ni++)
            #pragma unroll
            for (int e = 0; e < 4; e++) {
                int r = wm*32 + mi*16 + qr + ((e>=2)?8:0);
                int c = wn*16 + ni*8 + 2*qc + (e&1);
                int gt = tt*64 + r, gj = jt*64 + c;
                float v = (gj <= gt) ? acc[mi][ni][e]*scale + FcT[r] - FcJ[c] : -INFINITY;
                dst[(size_t)r*NN + c] = v;
            }
}

// ---------------- causal softmax ---------------------------------------------
__global__ void softmax_k() {
    int t = blockIdx.x, bh = blockIdx.y;
    int jmax = ((t >> 6) + 1) << 6;
    float* row = g_S + (size_t)bh*NN*NN + (size_t)t*NN;
    __shared__ float red[256];
    int tid = threadIdx.x;
    float m = -INFINITY;
    for (int j = tid; j < jmax; j += 256) m = fmaxf(m, row[j]);
    red[tid] = m; __syncthreads();
    for (int o = 128; o; o >>= 1) { if (tid < o) red[tid] = fmaxf(red[tid], red[tid+o]); __syncthreads(); }
    m = red[0]; __syncthreads();
    float s = 0.f;
    for (int j = tid; j < jmax; j += 256) { float e = expf(row[j] - m); row[j] = e; s += e; }
    red[tid] = s; __syncthreads();
    for (int o = 128; o; o >>= 1) { if (tid < o) red[tid] += red[tid+o]; __syncthreads(); }
    float inv = 1.f / red[0];
    for (int j = tid; j < jmax; j += 256) row[j] *= inv;
}

// ---------------- O_h = P @ V_h (causal tiles only) --------------------------
__global__ void pv_k() {
    int tm = blockIdx.x, bh = blockIdx.y;
    int b = bh / HH, h = bh % HH;
    extern __shared__ float sm[];
    float* tA[2] = {sm,        sm + 2*TSZ};   // P tiles [r][jj]
    float* tB[2] = {sm + TSZ,  sm + 3*TSZ};   // V tiles [jj][dd]
    int tid = threadIdx.x;
    int warp = tid >> 5, lane = tid & 31;
    int wm = warp >> 2, wn = warp & 3;
    int qr = lane >> 2, qc = lane & 3;
    float acc[2][2][4] = {};
    int n = tm + 1;
    cp_tile(g_S + (size_t)bh*NN*NN + (size_t)(tm*64)*NN, NN, tA[0], tid);
    cp_tile(g_v + (size_t)(b*NN)*DD + h*HD, DD, tB[0], tid);
    __pipeline_commit();
    for (int t = 0; t < n; t++) {
        if (t + 1 < n) {
            cp_tile(g_S + (size_t)bh*NN*NN + (size_t)(tm*64)*NN + (t+1)*64, NN, tA[(t+1)&1], tid);
            cp_tile(g_v + (size_t)(b*NN + (t+1)*64)*DD + h*HD, DD, tB[(t+1)&1], tid);
            __pipeline_commit();
        }
        __pipeline_wait_prior((t+1 < n) ? 1 : 0);
        __syncthreads();
        wmm64t<0,0>(tA[t&1], tB[t&1], acc, wm, wn, lane, false);
        __syncthreads();
    }
    float* dst = g_O + (size_t)(b*NN + tm*64)*DD + h*HD;
    #pragma unroll
    for (int mi = 0; mi < 2; mi++)
        #pragma unroll
        for (int ni = 0; ni < 2; ni++) {
            int r0 = wm*32 + mi*16 + qr;
            int c0 = wn*16 + ni*8 + 2*qc;
            *(float2*)(dst + (size_t)r0*DD + c0)     = make_float2(acc[mi][ni][0], acc[mi][ni][1]);
            *(float2*)(dst + (size_t)(r0+8)*DD + c0) = make_float2(acc[mi][ni][2], acc[mi][ni][3]);
        }
}

// -----------------------------------------------------------------------------
extern "C" void kernel_launch(void* const* d_in, const int* in_sizes, int n_in,
                              void* d_out, int out_size) {
    const float* x     = (const float*)d_in[0];
    const float* Wq    = (const float*)d_in[1];
    const float* Wk    = (const float*)d_in[2];
    const float* Wv    = (const float*)d_in[3];
    const float* Wo    = (const float*)d_in[4];
    const float* Ww1   = (const float*)d_in[5];
    const float* Ww2   = (const float*)d_in[6];
    const float* Wb    = (const float*)d_in[7];
    const float* Wf    = (const float*)d_in[8];
    const float* delta = (const float*)d_in[9];
    float* out = (float*)d_out;

    static bool attr_done = false;
    if (!attr_done) {
        cudaFuncSetAttribute(proj_small_k, cudaFuncAttributeMaxDynamicSharedMemorySize, (128*65 + 128*100)*4);
        cudaFuncSetAttribute(sgemm64_k,    cudaFuncAttributeMaxDynamicSharedMemorySize, 4*TSZ*4);
        cudaFuncSetAttribute(pre_k,        cudaFuncAttributeMaxDynamicSharedMemorySize, 2*TSZ*4);
        cudaFuncSetAttribute(solve2_k,     cudaFuncAttributeMaxDynamicSharedMemorySize, 4*TSZ*4);
        cudaFuncSetAttribute(scores2_k,    cudaFuncAttributeMaxDynamicSharedMemorySize, 5*TSZ*4);
        cudaFuncSetAttribute(pv_k,         cudaFuncAttributeMaxDynamicSharedMemorySize, 4*TSZ*4);
        attr_done = true;
    }

    float *pq, *pk, *pv, *pw, *pw1, *pO;
    cudaGetSymbolAddress((void**)&pq,  g_q);
    cudaGetSymbolAddress((void**)&pk,  g_k);
    cudaGetSymbolAddress((void**)&pv,  g_v);
    cudaGetSymbolAddress((void**)&pw,  g_w);
    cudaGetSymbolAddress((void**)&pw1, g_w1);
    cudaGetSymbolAddress((void**)&pO,  g_O);
    float *pC, *pL, *pG;
    cudaGetSymbolAddress((void**)&pC, g_C);
    cudaGetSymbolAddress((void**)&pL, g_L);
    cudaGetSymbolAddress((void**)&pG, g_G);

    const int M = BB*NN;   // 2048
    dim3 blk(256);
    dim3 gfull(M/64, DD/64);           // 32 x 16
    size_t smem2 = 2*TSZ*sizeof(float);
    size_t smem4 = 4*TSZ*sizeof(float);
    size_t smem5 = 5*TSZ*sizeof(float);

    // big projections
    sgemm64_k<<<gfull, blk, smem4>>>(x, Wq, pq, DD, DD, DD, DD);
    sgemm64_k<<<gfull, blk, smem4>>>(x, Wk, pk, DD, DD, DD, DD);
    sgemm64_k<<<gfull, blk, smem4>>>(x, Wv, pv, DD, DD, DD, DD);

    // fused skinny projections (w1 | xb | xf), split-K + reduce
    proj_small_k<<<dim3(M/64, 8), blk, (128*65 + 128*100)*4>>>(x, Ww1, Wb, Wf);
    proj_small_reduce_k<<<(2048*96 + 255)/256, 256>>>();

    // w = w1 @ Ww2  (K=64)
    sgemm64_k<<<gfull, blk, smem4>>>(pw1, Ww2, pw, HD, HD, DD, DD);

    // w normalize, gates, decay cumsum
    normw_k<<<(BB*NN*HH*32)/256, 256>>>();
    gates_k<<<(BB*NN*HH + 255)/256, 256>>>(delta);
    cumsum_k<<<BH, NN>>>();

    // precompute RHS (normal), L (transposed), G (transposed)
    dim3 gpre(NTRI, BH);
    pre_k<<<gpre, blk, smem2>>>(pw, pk, pC, /*diagKeepEq=*/0, /*useBeta=*/0, /*storeT=*/0);
    pre_k<<<gpre, blk, smem2>>>(pw, pw, pL, /*diagKeepEq=*/0, /*useBeta=*/1, /*storeT=*/1);
    pre_k<<<gpre, blk, smem2>>>(pq, pw, pG, /*diagKeepEq=*/1, /*useBeta=*/1, /*storeT=*/1);

    // blocked UT triangular solve: 16 sequential block-row steps
    for (int ib = 0; ib < NT; ib++)
        solve2_k<<<dim3(ib + 1, BH), blk, smem4>>>(ib);

    // logits, softmax, P@V, output projection
    scores2_k<<<dim3(NTRI, BH), blk, smem5>>>();
    softmax_k<<<dim3(NN, BH), 256>>>();
    pv_k<<<dim3(NT, BH), blk, smem4>>>();
    sgemm64_k<<<gfull, blk, smem4>>>(pO, Wo, out, DD, DD, DD, DD);
}